// round 1
// baseline (speedup 1.0000x reference)
#include <cuda_runtime.h>
#include <math.h>

// Problem constants
#define BB 8
#define MM 1024
#define DD 1024
#define HH 16
#define KHD 64
#define N3 3072   // 3*DD

// Scratch (allocation-free rule: __device__ globals)
__device__ float g_Q[BB*HH*MM*KHD];   // [bh][m][64]
__device__ float g_K[BB*HH*MM*KHD];
__device__ float g_V[BB*HH*MM*KHD];
__device__ float g_O[BB*MM*DD];       // [b*M + m][h*64 + k]

// ---------------------------------------------------------------------------
// SGEMM: 128x128 tile, BK=8, 256 threads, 8x8 per-thread microtile.
// MODE 0: C = A @ B (generic)
// MODE 1: QKV — A = x + z*M*K (batch via blockIdx.z), scatter into g_Q/g_K/g_V
// MODE 2: PROJ — A = g_O (device global), C = d_out
// ---------------------------------------------------------------------------
template<int MODE>
__global__ __launch_bounds__(256) void sgemm_kernel(
    const float* __restrict__ A, const float* __restrict__ Bm,
    float* __restrict__ C, int Mx, int Nx, int Kx)
{
    __shared__ float As[8][128];
    __shared__ float Bs[8][128];

    const int tid = threadIdx.x;
    const int bm = blockIdx.y, bn = blockIdx.x;

    const float* Abase = (MODE == 2) ? (const float*)g_O : A;
    const float* Ab = Abase + (size_t)blockIdx.z * (size_t)Mx * (size_t)Kx;

    // A tile load mapping: 128 rows x 8 cols -> each thread one float4
    const int arow = tid >> 1;            // 0..127
    const int acol = (tid & 1) * 4;       // 0 or 4
    // B tile load mapping: 8 rows x 128 cols -> each thread one float4
    const int brow = tid >> 5;            // 0..7
    const int bcol = (tid & 31) * 4;      // 0..124

    const int rowS = (tid >> 4) * 8;      // 0..120
    const int colS = (tid & 15) * 8;

    float acc[8][8];
    #pragma unroll
    for (int i = 0; i < 8; i++)
        #pragma unroll
        for (int j = 0; j < 8; j++) acc[i][j] = 0.f;

    const float* Aptr = Ab + (size_t)(bm*128 + arow) * Kx + acol;
    const float* Bptr = Bm + (size_t)brow * Nx + bn*128 + bcol;

    for (int kt = 0; kt < Kx; kt += 8) {
        float4 av = *(const float4*)(Aptr + kt);
        As[acol+0][arow] = av.x;
        As[acol+1][arow] = av.y;
        As[acol+2][arow] = av.z;
        As[acol+3][arow] = av.w;
        *(float4*)&Bs[brow][bcol] = *(const float4*)(Bptr + (size_t)kt * Nx);
        __syncthreads();

        #pragma unroll
        for (int k = 0; k < 8; k++) {
            float4 a0 = *(float4*)&As[k][rowS];
            float4 a1 = *(float4*)&As[k][rowS+4];
            float4 b0 = *(float4*)&Bs[k][colS];
            float4 b1 = *(float4*)&Bs[k][colS+4];
            float a[8] = {a0.x,a0.y,a0.z,a0.w,a1.x,a1.y,a1.z,a1.w};
            float b[8] = {b0.x,b0.y,b0.z,b0.w,b1.x,b1.y,b1.z,b1.w};
            #pragma unroll
            for (int i = 0; i < 8; i++)
                #pragma unroll
                for (int j = 0; j < 8; j++)
                    acc[i][j] = fmaf(a[i], b[j], acc[i][j]);
        }
        __syncthreads();
    }

    if (MODE == 1) {
        const int bz = blockIdx.z;
        #pragma unroll
        for (int i = 0; i < 8; i++) {
            const int m = bm*128 + rowS + i;
            #pragma unroll
            for (int j = 0; j < 8; j++) {
                const int c = bn*128 + colS + j;
                const int h = c / 192;
                const int r = c - h*192;
                const size_t base = ((size_t)((bz*HH + h)*MM + m)) * KHD;
                const float v = acc[i][j];
                if (r < 64)        g_Q[base + r]       = v;
                else if (r < 128)  g_K[base + r - 64]  = v;
                else               g_V[base + r - 128] = v;
            }
        }
    } else {
        #pragma unroll
        for (int i = 0; i < 8; i++) {
            const int row = bm*128 + rowS + i;
            float* Crow = C + (size_t)row * Nx + bn*128 + colS;
            *(float4*)(Crow)     = make_float4(acc[i][0], acc[i][1], acc[i][2], acc[i][3]);
            *(float4*)(Crow + 4) = make_float4(acc[i][4], acc[i][5], acc[i][6], acc[i][7]);
        }
    }
}

// ---------------------------------------------------------------------------
// Flash attention, fp32, causal. CTA = (q-tile of 64 rows, bh). 256 threads.
// Thread (ty,tx): rows ty*4..+3, cols tx*4..+3 of the 64x64 tile.
// Smem (dynamic): Qs[d][row] pad68 | Ks[d][key] pad68 | Ps[key][row] pad68 | Vs[key][d]
// ---------------------------------------------------------------------------
#define ATTN_SMEM_FLOATS (3*64*68 + 64*64)
#define ATTN_SMEM_BYTES  (ATTN_SMEM_FLOATS * 4)

__global__ __launch_bounds__(256) void attn_kernel()
{
    extern __shared__ float smem[];
    float* Qs = smem;               // [64][68]
    float* Ks = smem + 64*68;       // [64][68]
    float* Ps = smem + 2*64*68;     // [64][68]
    float* Vs = smem + 3*64*68;     // [64][64]

    const int tid = threadIdx.x;
    const int qt = gridDim.x - 1 - blockIdx.x;   // largest tiles scheduled first
    const int bh = blockIdx.y;
    const int q0 = qt * 64;

    const float* Qg = g_Q + (size_t)bh * MM * KHD;
    const float* Kg = g_K + (size_t)bh * MM * KHD;
    const float* Vg = g_V + (size_t)bh * MM * KHD;

    const int ty = tid >> 4, tx = tid & 15;

    // Load Q tile transposed: Qs[d][row]
    {
        const int r0 = tid >> 4;
        const int d4 = (tid & 15) * 4;
        for (int rr = r0; rr < 64; rr += 16) {
            float4 v = *(const float4*)(Qg + (size_t)(q0 + rr) * KHD + d4);
            Qs[(d4+0)*68 + rr] = v.x;
            Qs[(d4+1)*68 + rr] = v.y;
            Qs[(d4+2)*68 + rr] = v.z;
            Qs[(d4+3)*68 + rr] = v.w;
        }
    }

    float m_run[4], l_run[4], acc[4][4];
    #pragma unroll
    for (int r = 0; r < 4; r++) {
        m_run[r] = -1e30f; l_run[r] = 0.f;
        #pragma unroll
        for (int c = 0; c < 4; c++) acc[r][c] = 0.f;
    }

    for (int kt = 0; kt <= qt; kt++) {
        const int k0 = kt * 64;
        // Load K tile transposed, V tile direct
        {
            const int r0 = tid >> 4;
            const int d4 = (tid & 15) * 4;
            for (int rr = r0; rr < 64; rr += 16) {
                float4 v = *(const float4*)(Kg + (size_t)(k0 + rr) * KHD + d4);
                Ks[(d4+0)*68 + rr] = v.x;
                Ks[(d4+1)*68 + rr] = v.y;
                Ks[(d4+2)*68 + rr] = v.z;
                Ks[(d4+3)*68 + rr] = v.w;
            }
            #pragma unroll
            for (int t = 0; t < 4; t++) {
                const int fi  = tid + t*256;      // 0..1023 float4s
                const int key = fi >> 4;
                const int dd4 = (fi & 15) * 4;
                *(float4*)&Vs[key*64 + dd4] =
                    *(const float4*)(Vg + (size_t)(k0 + key) * KHD + dd4);
            }
        }
        __syncthreads();

        // S = Q @ K^T (4x4 microtile)
        float s[4][4];
        #pragma unroll
        for (int r = 0; r < 4; r++)
            #pragma unroll
            for (int c = 0; c < 4; c++) s[r][c] = 0.f;

        #pragma unroll 8
        for (int d = 0; d < 64; d++) {
            float4 a = *(float4*)&Qs[d*68 + ty*4];
            float4 b = *(float4*)&Ks[d*68 + tx*4];
            float ar[4] = {a.x,a.y,a.z,a.w};
            float bc[4] = {b.x,b.y,b.z,b.w};
            #pragma unroll
            for (int r = 0; r < 4; r++)
                #pragma unroll
                for (int c = 0; c < 4; c++)
                    s[r][c] = fmaf(ar[r], bc[c], s[r][c]);
        }

        // scale + causal mask (only the diagonal tile needs masking)
        const float sc = 0.125f;  // 1/sqrt(64)
        if (kt == qt) {
            #pragma unroll
            for (int r = 0; r < 4; r++)
                #pragma unroll
                for (int c = 0; c < 4; c++)
                    s[r][c] = ((tx*4 + c) <= (ty*4 + r)) ? s[r][c]*sc : -1e30f;
        } else {
            #pragma unroll
            for (int r = 0; r < 4; r++)
                #pragma unroll
                for (int c = 0; c < 4; c++)
                    s[r][c] *= sc;
        }

        // online softmax per row (reduce across the 16 lanes of the row group)
        #pragma unroll
        for (int r = 0; r < 4; r++) {
            float rm = fmaxf(fmaxf(s[r][0], s[r][1]), fmaxf(s[r][2], s[r][3]));
            #pragma unroll
            for (int o = 1; o < 16; o <<= 1)
                rm = fmaxf(rm, __shfl_xor_sync(0xffffffffu, rm, o, 16));
            const float mn = fmaxf(m_run[r], rm);
            const float scale = __expf(m_run[r] - mn);
            float psum = 0.f;
            #pragma unroll
            for (int c = 0; c < 4; c++) {
                const float p = __expf(s[r][c] - mn);
                s[r][c] = p;
                psum += p;
            }
            #pragma unroll
            for (int o = 1; o < 16; o <<= 1)
                psum += __shfl_xor_sync(0xffffffffu, psum, o, 16);
            l_run[r] = l_run[r] * scale + psum;
            m_run[r] = mn;
            #pragma unroll
            for (int c = 0; c < 4; c++) acc[r][c] *= scale;
        }

        // store P transposed: Ps[key][row]
        #pragma unroll
        for (int c = 0; c < 4; c++) {
            const int j = tx*4 + c;
            *(float4*)&Ps[j*68 + ty*4] =
                make_float4(s[0][c], s[1][c], s[2][c], s[3][c]);
        }
        __syncthreads();

        // O += P @ V
        #pragma unroll 8
        for (int key = 0; key < 64; key++) {
            float4 a = *(float4*)&Ps[key*68 + ty*4];
            float4 b = *(float4*)&Vs[key*64 + tx*4];
            float ar[4] = {a.x,a.y,a.z,a.w};
            float bc[4] = {b.x,b.y,b.z,b.w};
            #pragma unroll
            for (int r = 0; r < 4; r++)
                #pragma unroll
                for (int c = 0; c < 4; c++)
                    acc[r][c] = fmaf(ar[r], bc[c], acc[r][c]);
        }
        __syncthreads();
    }

    // Epilogue: normalize, write to g_O[b*M+m][h*64+k]
    const int b = bh >> 4, h = bh & 15;
    #pragma unroll
    for (int r = 0; r < 4; r++) {
        const float inv = 1.f / l_run[r];
        const int m = q0 + ty*4 + r;
        *(float4*)&g_O[((size_t)(b*MM + m)) * DD + h*64 + tx*4] =
            make_float4(acc[r][0]*inv, acc[r][1]*inv, acc[r][2]*inv, acc[r][3]*inv);
    }
}

// ---------------------------------------------------------------------------
extern "C" void kernel_launch(void* const* d_in, const int* in_sizes, int n_in,
                              void* d_out, int out_size)
{
    const float* x   = (const float*)d_in[0];
    const float* P_i = (const float*)d_in[1];
    const float* P_o = (const float*)d_in[2];
    float* y = (float*)d_out;

    cudaFuncSetAttribute(attn_kernel,
                         cudaFuncAttributeMaxDynamicSharedMemorySize,
                         ATTN_SMEM_BYTES);

    // 1) QKV projection: per batch X[1024,1024] @ P_i[1024,3072] -> Q/K/V scratch
    {
        dim3 grid(N3/128, MM/128, BB);
        sgemm_kernel<1><<<grid, 256>>>(x, P_i, nullptr, MM, N3, DD);
    }
    // 2) Causal flash attention (fp32)
    {
        dim3 grid(MM/64, BB*HH);
        attn_kernel<<<grid, 256, ATTN_SMEM_BYTES>>>();
    }
    // 3) Output projection: g_O[8192,1024] @ P_o[1024,1024] -> y
    {
        dim3 grid(DD/128, (BB*MM)/128, 1);
        sgemm_kernel<2><<<grid, 256>>>(nullptr, P_o, y, BB*MM, DD, DD);
    }
}

// round 2
// speedup vs baseline: 1.3879x; 1.3879x over previous
#include <cuda_runtime.h>
#include <math.h>
#include <stdint.h>

#define BB 8
#define MM 1024
#define DD 1024
#define HH 16
#define KHD 64
#define N3 3072

// Scratch (allocation-free rule: __device__ globals)
__device__ float g_Q[BB*HH*MM*KHD];   // [bh][m][64]
__device__ float g_K[BB*HH*MM*KHD];
__device__ float g_V[BB*HH*MM*KHD];
__device__ float g_O[BB*MM*DD];       // [b*M + m][h*64 + k]

// ---------------------------------------------------------------------------
// tf32 helpers: split fp32 into hi+lo tf32 pair (3xTF32 compensation scheme)
// ---------------------------------------------------------------------------
__device__ __forceinline__ void split2(float a, uint32_t& hi, uint32_t& lo){
    uint32_t h;
    asm("cvt.rna.tf32.f32 %0, %1;" : "=r"(h) : "f"(a));
    float lf = a - __uint_as_float(h);
    uint32_t l;
    asm("cvt.rna.tf32.f32 %0, %1;" : "=r"(l) : "f"(lf));
    hi = h; lo = l;
}
// split, results stored as float bit-patterns (for staging through smem)
__device__ __forceinline__ void split2f(float a, float& hi, float& lo){
    uint32_t h, l;
    split2(a, h, l);
    hi = __uint_as_float(h);
    lo = __uint_as_float(l);
}
__device__ __forceinline__ uint32_t fu(float a){ return __float_as_uint(a); }

__device__ __forceinline__ void mma8(float* d, const uint32_t* a,
                                     uint32_t b0, uint32_t b1){
    asm volatile("mma.sync.aligned.m16n8k8.row.col.f32.tf32.tf32.f32 "
        "{%0,%1,%2,%3},{%4,%5,%6,%7},{%8,%9},{%0,%1,%2,%3};"
        : "+f"(d[0]), "+f"(d[1]), "+f"(d[2]), "+f"(d[3])
        : "r"(a[0]), "r"(a[1]), "r"(a[2]), "r"(a[3]), "r"(b0), "r"(b1));
}

// ---------------------------------------------------------------------------
// 3xTF32 tensor-core GEMM: 128x128 tile, BK=32, 256 threads (8 warps).
// Warp grid 2(m) x 4(n), warp tile 64x32 -> 4 m-tiles x 4 n-tiles of m16n8k8.
// As[128][36]: bank = (4*row + k) mod 32 over the frag footprint -> conflict-free
// Bs[32][136]: bank = (8*k + n) mod 32 -> conflict-free
// Register-prefetch double buffering hides the gmem tile loads.
// MODE 1: QKV (A = x + z*M*K, scatter -> g_Q/g_K/g_V); MODE 2: proj (A = g_O)
// ---------------------------------------------------------------------------
template<int MODE>
__global__ __launch_bounds__(256) void gemm_tf32(
    const float* __restrict__ A, const float* __restrict__ Bm,
    float* __restrict__ C, int Mx, int Nx, int Kx)
{
    __shared__ float As[128][36];
    __shared__ float Bs[32][136];

    const int tid  = threadIdx.x;
    const int lane = tid & 31, wid = tid >> 5;
    const int wm = wid >> 2, wn = wid & 3;
    const int bm = blockIdx.y, bn = blockIdx.x;

    const float* Abase = (MODE == 2) ? (const float*)g_O : A;
    const float* Ab = Abase + (size_t)blockIdx.z * (size_t)Mx * (size_t)Kx;

    float4 pa[4], pb[4];
    // initial prefetch (tile kt=0)
    #pragma unroll
    for (int it = 0; it < 4; it++){
        int idx = tid + it*256;
        int r = idx >> 3, kc = (idx & 7) << 2;
        pa[it] = *(const float4*)(Ab + (size_t)(bm*128 + r)*Kx + kc);
        int kb = idx >> 5, n4 = (idx & 31) << 2;
        pb[it] = *(const float4*)(Bm + (size_t)kb*Nx + bn*128 + n4);
    }

    float acc[4][4][4];
    #pragma unroll
    for (int mt = 0; mt < 4; mt++)
        #pragma unroll
        for (int nt = 0; nt < 4; nt++)
            #pragma unroll
            for (int c = 0; c < 4; c++) acc[mt][nt][c] = 0.f;

    for (int kt = 0; kt < Kx; kt += 32){
        // store prefetched tile
        #pragma unroll
        for (int it = 0; it < 4; it++){
            int idx = tid + it*256;
            int r = idx >> 3, kc = (idx & 7) << 2;
            *(float4*)&As[r][kc] = pa[it];
            int kb = idx >> 5, n4 = (idx & 31) << 2;
            *(float4*)&Bs[kb][n4] = pb[it];
        }
        __syncthreads();
        // prefetch next tile into regs (overlaps with compute below)
        if (kt + 32 < Kx){
            #pragma unroll
            for (int it = 0; it < 4; it++){
                int idx = tid + it*256;
                int r = idx >> 3, kc = (idx & 7) << 2;
                pa[it] = *(const float4*)(Ab + (size_t)(bm*128 + r)*Kx + (kt+32) + kc);
                int kb = idx >> 5, n4 = (idx & 31) << 2;
                pb[it] = *(const float4*)(Bm + (size_t)(kt+32 + kb)*Nx + bn*128 + n4);
            }
        }
        // compute 4 k-steps of 8
        #pragma unroll
        for (int kk = 0; kk < 4; kk++){
            const int k = kk*8;
            uint32_t ah[4][4], al[4][4];
            #pragma unroll
            for (int mt = 0; mt < 4; mt++){
                int r0 = wm*64 + mt*16 + (lane>>2);
                int c0 = k + (lane&3);
                split2(As[r0][c0],     ah[mt][0], al[mt][0]);
                split2(As[r0+8][c0],   ah[mt][1], al[mt][1]);
                split2(As[r0][c0+4],   ah[mt][2], al[mt][2]);
                split2(As[r0+8][c0+4], ah[mt][3], al[mt][3]);
            }
            #pragma unroll
            for (int nt = 0; nt < 4; nt++){
                int nc = wn*32 + nt*8 + (lane>>2);
                int kr = k + (lane&3);
                uint32_t b0h, b0l, b1h, b1l;
                split2(Bs[kr][nc],   b0h, b0l);
                split2(Bs[kr+4][nc], b1h, b1l);
                #pragma unroll
                for (int mt = 0; mt < 4; mt++){
                    mma8(acc[mt][nt], ah[mt], b0h, b1h);
                    mma8(acc[mt][nt], ah[mt], b0l, b1l);
                    mma8(acc[mt][nt], al[mt], b0h, b1h);
                }
            }
        }
        __syncthreads();
    }

    // epilogue
    if (MODE == 1){
        const int bz = blockIdx.z;
        #pragma unroll
        for (int mt = 0; mt < 4; mt++)
            #pragma unroll
            for (int nt = 0; nt < 4; nt++)
                #pragma unroll
                for (int c = 0; c < 4; c++){
                    int row = bm*128 + wm*64 + mt*16 + (lane>>2) + ((c>>1)<<3);
                    int col = bn*128 + wn*32 + nt*8 + ((lane&3)<<1) + (c&1);
                    int h = col / 192;
                    int r = col - h*192;
                    size_t base = ((size_t)((bz*HH + h)*MM + row))*KHD;
                    float v = acc[mt][nt][c];
                    if (r < 64)        g_Q[base + r]        = v;
                    else if (r < 128)  g_K[base + r - 64]   = v;
                    else               g_V[base + r - 128]  = v;
                }
    } else {
        #pragma unroll
        for (int mt = 0; mt < 4; mt++)
            #pragma unroll
            for (int nt = 0; nt < 4; nt++){
                int row = bm*128 + wm*64 + mt*16 + (lane>>2);
                int col = bn*128 + wn*32 + nt*8 + ((lane&3)<<1);
                *(float2*)&C[(size_t)row*Nx + col] =
                    make_float2(acc[mt][nt][0], acc[mt][nt][1]);
                *(float2*)&C[(size_t)(row+8)*Nx + col] =
                    make_float2(acc[mt][nt][2], acc[mt][nt][3]);
            }
    }
}

// ---------------------------------------------------------------------------
// Tensor-core causal flash attention (3xTF32).
// CTA: 256 threads (8 warps), q-tile = 128 rows, kv-tile = 64. Warp w owns
// rows w*16..+15. Q frags persistent in regs (hi/lo). K/V split hi/lo once
// cooperatively into smem. P staged to smem (warp-local rows -> __syncwarp).
// Smem: Ps[128][68] (Q staging, then P) | Kh,Kl[64][68] | Vh,Vl[64][72]
// All frag LDS patterns are bank-conflict-free by pad choice.
// ---------------------------------------------------------------------------
#define ATTN_SMEM_BYTES ((128*68 + 2*64*68 + 2*64*72)*4)

__global__ __launch_bounds__(256) void attn_tc()
{
    extern __shared__ float smf[];
    float* Ps = smf;                       // [128][68]
    float* Kh = smf + 128*68;              // [64][68]
    float* Kl = Kh + 64*68;                // [64][68]
    float* Vh = Kl + 64*68;                // [64][72]
    float* Vl = Vh + 64*72;                // [64][72]

    const int tid = threadIdx.x, lane = tid & 31, wid = tid >> 5;
    const int qt = gridDim.x - 1 - blockIdx.x;   // biggest tiles first
    const int bh = blockIdx.y;
    const int q0 = qt * 128;

    const float* Qg = g_Q + (size_t)bh*MM*KHD;
    const float* Kg = g_K + (size_t)bh*MM*KHD;
    const float* Vg = g_V + (size_t)bh*MM*KHD;

    // stage Q tile [128][64] into smem (coalesced), then extract frags
    #pragma unroll
    for (int it = 0; it < 8; it++){
        int idx = tid + it*256;
        int r = idx >> 4, d4 = (idx & 15) << 2;
        *(float4*)&Ps[r*68 + d4] = *(const float4*)(Qg + (size_t)(q0 + r)*KHD + d4);
    }
    __syncthreads();

    uint32_t qh[8][4], ql[8][4];
    const int rA = wid*16 + (lane>>2);
    #pragma unroll
    for (int kk = 0; kk < 8; kk++){
        int c = kk*8 + (lane&3);
        split2(Ps[rA*68 + c],         qh[kk][0], ql[kk][0]);
        split2(Ps[(rA+8)*68 + c],     qh[kk][1], ql[kk][1]);
        split2(Ps[rA*68 + c + 4],     qh[kk][2], ql[kk][2]);
        split2(Ps[(rA+8)*68 + c + 4], qh[kk][3], ql[kk][3]);
    }

    float o[8][4];
    #pragma unroll
    for (int nt = 0; nt < 8; nt++)
        #pragma unroll
        for (int c = 0; c < 4; c++) o[nt][c] = 0.f;
    float m_run[2] = {-1e30f, -1e30f};
    float l_run[2] = {0.f, 0.f};

    const int ktEnd = 2*qt + 1;
    for (int kt = 0; kt <= ktEnd; kt++){
        const int k0 = kt*64;
        __syncthreads();                       // Kh/Kl/Vh/Vl free for reuse
        // cooperative load + hi/lo split of K and V tiles
        #pragma unroll
        for (int it = 0; it < 4; it++){
            int idx = tid + it*256;
            int key = idx >> 4, d4 = (idx & 15) << 2;
            float4 kv = *(const float4*)(Kg + (size_t)(k0+key)*KHD + d4);
            float4 hv, lv;
            split2f(kv.x, hv.x, lv.x); split2f(kv.y, hv.y, lv.y);
            split2f(kv.z, hv.z, lv.z); split2f(kv.w, hv.w, lv.w);
            *(float4*)&Kh[key*68 + d4] = hv;
            *(float4*)&Kl[key*68 + d4] = lv;
            float4 vv = *(const float4*)(Vg + (size_t)(k0+key)*KHD + d4);
            split2f(vv.x, hv.x, lv.x); split2f(vv.y, hv.y, lv.y);
            split2f(vv.z, hv.z, lv.z); split2f(vv.w, hv.w, lv.w);
            *(float4*)&Vh[key*72 + d4] = hv;
            *(float4*)&Vl[key*72 + d4] = lv;
        }
        __syncthreads();

        // S = Q @ K^T  (per warp: 16 rows x 64 keys)
        float s[8][4];
        #pragma unroll
        for (int nt = 0; nt < 8; nt++)
            #pragma unroll
            for (int c = 0; c < 4; c++) s[nt][c] = 0.f;

        #pragma unroll
        for (int kk = 0; kk < 8; kk++){
            #pragma unroll
            for (int nt = 0; nt < 8; nt++){
                int keyb = nt*8 + (lane>>2);
                int dc = kk*8 + (lane&3);
                uint32_t b0h = fu(Kh[keyb*68 + dc]);
                uint32_t b1h = fu(Kh[keyb*68 + dc + 4]);
                uint32_t b0l = fu(Kl[keyb*68 + dc]);
                uint32_t b1l = fu(Kl[keyb*68 + dc + 4]);
                mma8(s[nt], qh[kk], b0h, b1h);
                mma8(s[nt], qh[kk], b0l, b1l);
                mma8(s[nt], ql[kk], b0h, b1h);
            }
        }

        // scale + causal mask (only tiles touching the diagonal)
        const bool needMask = (kt >= 2*qt);
        #pragma unroll
        for (int nt = 0; nt < 8; nt++)
            #pragma unroll
            for (int c = 0; c < 4; c++){
                int rowL = wid*16 + (lane>>2) + ((c>>1)<<3);
                int colL = nt*8 + ((lane&3)<<1) + (c&1);
                float v = s[nt][c] * 0.125f;
                if (needMask && (k0 + colL > q0 + rowL)) v = -1e30f;
                s[nt][c] = v;
            }

        // online softmax per row-half (rows rA for c0/c1, rA+8 for c2/c3)
        #pragma unroll
        for (int hf = 0; hf < 2; hf++){
            float rm = -1e30f;
            #pragma unroll
            for (int nt = 0; nt < 8; nt++)
                rm = fmaxf(rm, fmaxf(s[nt][2*hf], s[nt][2*hf+1]));
            rm = fmaxf(rm, __shfl_xor_sync(0xffffffffu, rm, 1));
            rm = fmaxf(rm, __shfl_xor_sync(0xffffffffu, rm, 2));
            float mn  = fmaxf(m_run[hf], rm);
            float scl = __expf(m_run[hf] - mn);
            float psum = 0.f;
            #pragma unroll
            for (int nt = 0; nt < 8; nt++){
                float p0 = __expf(s[nt][2*hf]   - mn);
                float p1 = __expf(s[nt][2*hf+1] - mn);
                s[nt][2*hf] = p0; s[nt][2*hf+1] = p1;
                psum += p0 + p1;
            }
            psum += __shfl_xor_sync(0xffffffffu, psum, 1);
            psum += __shfl_xor_sync(0xffffffffu, psum, 2);
            l_run[hf] = l_run[hf]*scl + psum;
            m_run[hf] = mn;
            #pragma unroll
            for (int nt = 0; nt < 8; nt++){
                o[nt][2*hf]   *= scl;
                o[nt][2*hf+1] *= scl;
            }
        }

        // stage P (warp-local rows only)
        #pragma unroll
        for (int nt = 0; nt < 8; nt++){
            int colL = nt*8 + ((lane&3)<<1);
            *(float2*)&Ps[rA*68 + colL]     = make_float2(s[nt][0], s[nt][1]);
            *(float2*)&Ps[(rA+8)*68 + colL] = make_float2(s[nt][2], s[nt][3]);
        }
        __syncwarp();

        // O += P @ V
        #pragma unroll
        for (int kk = 0; kk < 8; kk++){
            uint32_t ah[4], al[4];
            int c = kk*8 + (lane&3);
            split2(Ps[rA*68 + c],         ah[0], al[0]);
            split2(Ps[(rA+8)*68 + c],     ah[1], al[1]);
            split2(Ps[rA*68 + c + 4],     ah[2], al[2]);
            split2(Ps[(rA+8)*68 + c + 4], ah[3], al[3]);
            #pragma unroll
            for (int nt = 0; nt < 8; nt++){
                int dcol = nt*8 + (lane>>2);
                int keyb = kk*8 + (lane&3);
                uint32_t b0h = fu(Vh[keyb*72 + dcol]);
                uint32_t b1h = fu(Vh[(keyb+4)*72 + dcol]);
                uint32_t b0l = fu(Vl[keyb*72 + dcol]);
                uint32_t b1l = fu(Vl[(keyb+4)*72 + dcol]);
                mma8(o[nt], ah, b0h, b1h);
                mma8(o[nt], ah, b0l, b1l);
                mma8(o[nt], al, b0h, b1h);
            }
        }
    }

    // epilogue: normalize and write g_O[b*M+m][h*64+d]
    const int b = bh >> 4, h = bh & 15;
    const float inv0 = 1.f / l_run[0], inv1 = 1.f / l_run[1];
    #pragma unroll
    for (int nt = 0; nt < 8; nt++){
        int d0 = nt*8 + ((lane&3)<<1);
        int m0 = q0 + rA;
        *(float2*)&g_O[((size_t)(b*MM + m0))*DD + h*64 + d0] =
            make_float2(o[nt][0]*inv0, o[nt][1]*inv0);
        *(float2*)&g_O[((size_t)(b*MM + m0 + 8))*DD + h*64 + d0] =
            make_float2(o[nt][2]*inv1, o[nt][3]*inv1);
    }
}

// ---------------------------------------------------------------------------
extern "C" void kernel_launch(void* const* d_in, const int* in_sizes, int n_in,
                              void* d_out, int out_size)
{
    const float* x   = (const float*)d_in[0];
    const float* P_i = (const float*)d_in[1];
    const float* P_o = (const float*)d_in[2];
    float* y = (float*)d_out;

    cudaFuncSetAttribute(attn_tc,
                         cudaFuncAttributeMaxDynamicSharedMemorySize,
                         ATTN_SMEM_BYTES);

    // 1) QKV projection: per batch X[1024,1024] @ P_i[1024,3072]
    {
        dim3 grid(N3/128, MM/128, BB);
        gemm_tf32<1><<<grid, 256>>>(x, P_i, nullptr, MM, N3, DD);
    }
    // 2) Causal flash attention (3xTF32 tensor)
    {
        dim3 grid(MM/128, BB*HH);
        attn_tc<<<grid, 256, ATTN_SMEM_BYTES>>>();
    }
    // 3) Output projection: g_O[8192,1024] @ P_o[1024,1024] -> y
    {
        dim3 grid(DD/128, (BB*MM)/128, 1);
        gemm_tf32<2><<<grid, 256>>>(nullptr, P_o, y, BB*MM, DD, DD);
    }
}

// round 3
// speedup vs baseline: 2.1143x; 1.5234x over previous
#include <cuda_runtime.h>
#include <cuda_bf16.h>
#include <math.h>
#include <stdint.h>

#define BB 8
#define MM 1024
#define DD 1024
#define HH 16
#define KHD 64
#define N3 3072

// Scratch (allocation-free rule: __device__ globals)
__device__ float g_Q[BB*HH*MM*KHD];   // [bh][m][64]
__device__ float g_K[BB*HH*MM*KHD];
__device__ float g_V[BB*HH*MM*KHD];
__device__ float g_O[BB*MM*DD];       // [b*M + m][h*64 + k]

// ---------------------------------------------------------------------------
// bf16 split helpers: a = hi + lo at bf16 precision, packed as bf16x2 (k-pairs)
// ---------------------------------------------------------------------------
__device__ __forceinline__ uint32_t bpack(float x, float y){
    __nv_bfloat162 h = __floats2bfloat162_rn(x, y);
    return *reinterpret_cast<uint32_t*>(&h);
}
__device__ __forceinline__ uint32_t bsplit(float x, float y, float& rx, float& ry){
    __nv_bfloat162 h = __floats2bfloat162_rn(x, y);
    rx = x - __low2float(h);
    ry = y - __high2float(h);
    return *reinterpret_cast<uint32_t*>(&h);
}

__device__ __forceinline__ void mma16(float* d, const uint32_t* a,
                                      uint32_t b0, uint32_t b1){
    asm volatile("mma.sync.aligned.m16n8k16.row.col.f32.bf16.bf16.f32 "
        "{%0,%1,%2,%3},{%4,%5,%6,%7},{%8,%9},{%0,%1,%2,%3};"
        : "+f"(d[0]), "+f"(d[1]), "+f"(d[2]), "+f"(d[3])
        : "r"(a[0]), "r"(a[1]), "r"(a[2]), "r"(a[3]), "r"(b0), "r"(b1));
}

// ---------------------------------------------------------------------------
// 3x-bf16 tensor GEMM: 128x128 tile, BK=32, 256 threads (8 warps, 2m x 4n),
// warp tile 64x32 -> 4 mt x 4 nt of m16n8k16. Operands pre-split hi/lo bf16
// and packed as k-adjacent pairs in smem; inner loop is LDS.32 + HMMA only.
//   Ah/Al[row 128][kp 16 +4pad]  (bank = 20r+c  : conflict-free)
//   Bh/Bl[kp 16][n 128 +8pad]    (bank = 8c+r   : conflict-free)
// Register-prefetch double buffering hides gmem tile loads.
// MODE 1: QKV (A = x + z*M*K, scatter -> g_Q/g_K/g_V); MODE 2: proj (A = g_O)
// ---------------------------------------------------------------------------
template<int MODE>
__global__ __launch_bounds__(256) void gemm_bf16x3(
    const float* __restrict__ A, const float* __restrict__ Bm,
    float* __restrict__ C, int Mx, int Nx, int Kx)
{
    __shared__ uint32_t Ah[128][20], Al[128][20];
    __shared__ uint32_t Bh[16][136],  Bl[16][136];

    const int tid  = threadIdx.x;
    const int lane = tid & 31, wid = tid >> 5;
    const int wm = wid >> 2, wn = wid & 3;
    const int bm = blockIdx.y, bn = blockIdx.x;

    const float* Abase = (MODE == 2) ? (const float*)g_O : A;
    const float* Ab = Abase + (size_t)blockIdx.z * (size_t)Mx * (size_t)Kx;

    float4 pa[4];
    float2 pb0[4], pb1[4];
    // initial prefetch (kt = 0)
    #pragma unroll
    for (int it = 0; it < 4; it++){
        int idx = tid + it*256;
        int r = idx >> 3, kc = (idx & 7) << 2;
        pa[it] = *(const float4*)(Ab + (size_t)(bm*128 + r)*Kx + kc);
        int kp = idx >> 6, nn = (idx & 63) << 1;
        pb0[it] = *(const float2*)(Bm + (size_t)(2*kp)*Nx   + bn*128 + nn);
        pb1[it] = *(const float2*)(Bm + (size_t)(2*kp+1)*Nx + bn*128 + nn);
    }

    float acc[4][4][4];
    #pragma unroll
    for (int mt = 0; mt < 4; mt++)
        #pragma unroll
        for (int nt = 0; nt < 4; nt++)
            #pragma unroll
            for (int c = 0; c < 4; c++) acc[mt][nt][c] = 0.f;

    for (int kt = 0; kt < Kx; kt += 32){
        // split + pack + store the prefetched tile
        #pragma unroll
        for (int it = 0; it < 4; it++){
            int idx = tid + it*256;
            int r = idx >> 3, kp0 = (idx & 7) << 1;
            float4 v = pa[it];
            float rx, ry;
            Ah[r][kp0]   = bsplit(v.x, v.y, rx, ry);
            Al[r][kp0]   = bpack(rx, ry);
            Ah[r][kp0+1] = bsplit(v.z, v.w, rx, ry);
            Al[r][kp0+1] = bpack(rx, ry);
            int kp = idx >> 6, nn = (idx & 63) << 1;
            float2 u = pb0[it], w = pb1[it];
            Bh[kp][nn]   = bsplit(u.x, w.x, rx, ry);
            Bl[kp][nn]   = bpack(rx, ry);
            Bh[kp][nn+1] = bsplit(u.y, w.y, rx, ry);
            Bl[kp][nn+1] = bpack(rx, ry);
        }
        __syncthreads();
        // prefetch next tile (registers only, overlaps compute)
        if (kt + 32 < Kx){
            #pragma unroll
            for (int it = 0; it < 4; it++){
                int idx = tid + it*256;
                int r = idx >> 3, kc = (idx & 7) << 2;
                pa[it] = *(const float4*)(Ab + (size_t)(bm*128 + r)*Kx + (kt+32) + kc);
                int kp = idx >> 6, nn = (idx & 63) << 1;
                pb0[it] = *(const float2*)(Bm + (size_t)(kt+32 + 2*kp)*Nx   + bn*128 + nn);
                pb1[it] = *(const float2*)(Bm + (size_t)(kt+32 + 2*kp+1)*Nx + bn*128 + nn);
            }
        }
        // 2 k16 steps
        #pragma unroll
        for (int kk = 0; kk < 2; kk++){
            uint32_t afh[4][4], afl[4][4];
            #pragma unroll
            for (int mt = 0; mt < 4; mt++){
                int r0 = wm*64 + mt*16 + (lane>>2);
                int c0 = kk*8 + (lane&3);
                afh[mt][0] = Ah[r0][c0];     afl[mt][0] = Al[r0][c0];
                afh[mt][1] = Ah[r0+8][c0];   afl[mt][1] = Al[r0+8][c0];
                afh[mt][2] = Ah[r0][c0+4];   afl[mt][2] = Al[r0][c0+4];
                afh[mt][3] = Ah[r0+8][c0+4]; afl[mt][3] = Al[r0+8][c0+4];
            }
            #pragma unroll
            for (int nt = 0; nt < 4; nt++){
                int nc = wn*32 + nt*8 + (lane>>2);
                int kr = kk*8 + (lane&3);
                uint32_t b0h = Bh[kr][nc],   b1h = Bh[kr+4][nc];
                uint32_t b0l = Bl[kr][nc],   b1l = Bl[kr+4][nc];
                #pragma unroll
                for (int mt = 0; mt < 4; mt++){
                    mma16(acc[mt][nt], afh[mt], b0h, b1h);
                    mma16(acc[mt][nt], afh[mt], b0l, b1l);
                    mma16(acc[mt][nt], afl[mt], b0h, b1h);
                }
            }
        }
        __syncthreads();
    }

    // epilogue
    if (MODE == 1){
        const int bz = blockIdx.z;
        #pragma unroll
        for (int mt = 0; mt < 4; mt++)
            #pragma unroll
            for (int nt = 0; nt < 4; nt++)
                #pragma unroll
                for (int c = 0; c < 4; c++){
                    int row = bm*128 + wm*64 + mt*16 + (lane>>2) + ((c>>1)<<3);
                    int col = bn*128 + wn*32 + nt*8 + ((lane&3)<<1) + (c&1);
                    int h = col / 192;
                    int r = col - h*192;
                    size_t base = ((size_t)((bz*HH + h)*MM + row))*KHD;
                    float v = acc[mt][nt][c];
                    if (r < 64)        g_Q[base + r]        = v;
                    else if (r < 128)  g_K[base + r - 64]   = v;
                    else               g_V[base + r - 128]  = v;
                }
    } else {
        #pragma unroll
        for (int mt = 0; mt < 4; mt++)
            #pragma unroll
            for (int nt = 0; nt < 4; nt++){
                int row = bm*128 + wm*64 + mt*16 + (lane>>2);
                int col = bn*128 + wn*32 + nt*8 + ((lane&3)<<1);
                *(float2*)&C[(size_t)row*Nx + col] =
                    make_float2(acc[mt][nt][0], acc[mt][nt][1]);
                *(float2*)&C[(size_t)(row+8)*Nx + col] =
                    make_float2(acc[mt][nt][2], acc[mt][nt][3]);
            }
    }
}

// ---------------------------------------------------------------------------
// 3x-bf16 causal flash attention. 256 threads (8 warps), q-tile 128, kv 64.
// Warp w owns rows w*16..+15. Q pre-split into register frags. K/V split+packed
// once per tile into smem. P packed hi/lo bf16x2 at store (cols already paired
// in the mma output layout).
// smem (u32): Pph[128][36] Ppl[128][36] | Kh,Kl[32][73] | Vh,Vl[32][72]
//   Q fp32 staging [128][68] overlays the Pp area (freed before first P store)
// ---------------------------------------------------------------------------
#define ATTN_SMEM_U32 (2*128*36 + 2*32*73 + 2*32*72)
#define ATTN_SMEM_BYTES (ATTN_SMEM_U32*4)

__global__ __launch_bounds__(256) void attn_tc()
{
    extern __shared__ uint32_t smu[];
    uint32_t* Pph = smu;                   // [128][36]
    uint32_t* Ppl = Pph + 128*36;
    uint32_t* Khs = Ppl + 128*36;          // [32][73]
    uint32_t* Kls = Khs + 32*73;
    uint32_t* Vhs = Kls + 32*73;           // [32][72]
    uint32_t* Vls = Vhs + 32*72;
    float* Qst = (float*)smu;              // [128][68] overlay on Pp area

    const int tid = threadIdx.x, lane = tid & 31, wid = tid >> 5;
    const int qt = gridDim.x - 1 - blockIdx.x;   // biggest tiles first
    const int bh = blockIdx.y;
    const int q0 = qt * 128;

    const float* Qg = g_Q + (size_t)bh*MM*KHD;
    const float* Kg = g_K + (size_t)bh*MM*KHD;
    const float* Vg = g_V + (size_t)bh*MM*KHD;

    // stage Q tile [128][64] fp32 (coalesced), then pre-split register frags
    #pragma unroll
    for (int it = 0; it < 8; it++){
        int idx = tid + it*256;
        int r = idx >> 4, d4 = (idx & 15) << 2;
        *(float4*)&Qst[r*68 + d4] = *(const float4*)(Qg + (size_t)(q0 + r)*KHD + d4);
    }
    __syncthreads();

    const int rA = wid*16 + (lane>>2);
    uint32_t qh[4][4], ql[4][4];
    #pragma unroll
    for (int kk = 0; kk < 4; kk++){
        int c = kk*16 + ((lane&3)<<1);
        float2 v00 = *(float2*)&Qst[rA*68 + c];
        float2 v10 = *(float2*)&Qst[(rA+8)*68 + c];
        float2 v01 = *(float2*)&Qst[rA*68 + c + 8];
        float2 v11 = *(float2*)&Qst[(rA+8)*68 + c + 8];
        float rx, ry;
        qh[kk][0] = bsplit(v00.x, v00.y, rx, ry); ql[kk][0] = bpack(rx, ry);
        qh[kk][1] = bsplit(v10.x, v10.y, rx, ry); ql[kk][1] = bpack(rx, ry);
        qh[kk][2] = bsplit(v01.x, v01.y, rx, ry); ql[kk][2] = bpack(rx, ry);
        qh[kk][3] = bsplit(v11.x, v11.y, rx, ry); ql[kk][3] = bpack(rx, ry);
    }

    float o[8][4];
    #pragma unroll
    for (int nt = 0; nt < 8; nt++)
        #pragma unroll
        for (int c = 0; c < 4; c++) o[nt][c] = 0.f;
    float m_run[2] = {-1e30f, -1e30f};
    float l_run[2] = {0.f, 0.f};

    const int ktEnd = 2*qt + 1;
    for (int kt = 0; kt <= ktEnd; kt++){
        const int k0 = kt*64;
        __syncthreads();          // smem tiles free for reuse (also guards Qst)
        // K: pack pairs along d.  V: pack pairs along key.
        #pragma unroll
        for (int it = 0; it < 4; it++){
            int idx = tid + it*256;
            {   // K
                int key = idx >> 4, dp0 = (idx & 15) << 1;
                float4 kv = *(const float4*)(Kg + (size_t)(k0+key)*KHD + (dp0<<1));
                float rx, ry;
                Khs[dp0*73 + key]     = bsplit(kv.x, kv.y, rx, ry);
                Kls[dp0*73 + key]     = bpack(rx, ry);
                Khs[(dp0+1)*73 + key] = bsplit(kv.z, kv.w, rx, ry);
                Kls[(dp0+1)*73 + key] = bpack(rx, ry);
            }
            {   // V
                int kp = idx >> 5, d2 = (idx & 31) << 1;
                float2 a = *(const float2*)(Vg + (size_t)(k0+2*kp)*KHD + d2);
                float2 b = *(const float2*)(Vg + (size_t)(k0+2*kp+1)*KHD + d2);
                float rx, ry;
                Vhs[kp*72 + d2]   = bsplit(a.x, b.x, rx, ry);
                Vls[kp*72 + d2]   = bpack(rx, ry);
                Vhs[kp*72 + d2+1] = bsplit(a.y, b.y, rx, ry);
                Vls[kp*72 + d2+1] = bpack(rx, ry);
            }
        }
        __syncthreads();

        // S = Q @ K^T
        float s[8][4];
        #pragma unroll
        for (int nt = 0; nt < 8; nt++)
            #pragma unroll
            for (int c = 0; c < 4; c++) s[nt][c] = 0.f;

        #pragma unroll
        for (int kk = 0; kk < 4; kk++){
            int dpc = kk*8 + (lane&3);
            #pragma unroll
            for (int nt = 0; nt < 8; nt++){
                int keyb = nt*8 + (lane>>2);
                uint32_t b0h = Khs[dpc*73 + keyb],     b1h = Khs[(dpc+4)*73 + keyb];
                uint32_t b0l = Kls[dpc*73 + keyb],     b1l = Kls[(dpc+4)*73 + keyb];
                mma16(s[nt], qh[kk], b0h, b1h);
                mma16(s[nt], qh[kk], b0l, b1l);
                mma16(s[nt], ql[kk], b0h, b1h);
            }
        }

        // scale + causal mask (only tiles touching the diagonal)
        const bool needMask = (kt >= 2*qt);
        #pragma unroll
        for (int nt = 0; nt < 8; nt++)
            #pragma unroll
            for (int c = 0; c < 4; c++){
                int rowL = wid*16 + (lane>>2) + ((c>>1)<<3);
                int colL = nt*8 + ((lane&3)<<1) + (c&1);
                float v = s[nt][c] * 0.125f;
                if (needMask && (k0 + colL > q0 + rowL)) v = -1e30f;
                s[nt][c] = v;
            }

        // online softmax per row-half
        #pragma unroll
        for (int hf = 0; hf < 2; hf++){
            float rm = -1e30f;
            #pragma unroll
            for (int nt = 0; nt < 8; nt++)
                rm = fmaxf(rm, fmaxf(s[nt][2*hf], s[nt][2*hf+1]));
            rm = fmaxf(rm, __shfl_xor_sync(0xffffffffu, rm, 1));
            rm = fmaxf(rm, __shfl_xor_sync(0xffffffffu, rm, 2));
            float mn  = fmaxf(m_run[hf], rm);
            float scl = __expf(m_run[hf] - mn);
            float psum = 0.f;
            #pragma unroll
            for (int nt = 0; nt < 8; nt++){
                float p0 = __expf(s[nt][2*hf]   - mn);
                float p1 = __expf(s[nt][2*hf+1] - mn);
                s[nt][2*hf] = p0; s[nt][2*hf+1] = p1;
                psum += p0 + p1;
            }
            psum += __shfl_xor_sync(0xffffffffu, psum, 1);
            psum += __shfl_xor_sync(0xffffffffu, psum, 2);
            l_run[hf] = l_run[hf]*scl + psum;
            m_run[hf] = mn;
            #pragma unroll
            for (int nt = 0; nt < 8; nt++){
                o[nt][2*hf]   *= scl;
                o[nt][2*hf+1] *= scl;
            }
        }

        // store P packed hi/lo (warp-local rows)
        #pragma unroll
        for (int nt = 0; nt < 8; nt++){
            int kp = nt*4 + (lane&3);
            float rx, ry;
            Pph[rA*36 + kp]     = bsplit(s[nt][0], s[nt][1], rx, ry);
            Ppl[rA*36 + kp]     = bpack(rx, ry);
            Pph[(rA+8)*36 + kp] = bsplit(s[nt][2], s[nt][3], rx, ry);
            Ppl[(rA+8)*36 + kp] = bpack(rx, ry);
        }
        __syncwarp();

        // O += P @ V
        #pragma unroll
        for (int kk = 0; kk < 4; kk++){
            int kpc = kk*8 + (lane&3);
            uint32_t ah[4], al[4];
            ah[0] = Pph[rA*36 + kpc];       al[0] = Ppl[rA*36 + kpc];
            ah[1] = Pph[(rA+8)*36 + kpc];   al[1] = Ppl[(rA+8)*36 + kpc];
            ah[2] = Pph[rA*36 + kpc + 4];   al[2] = Ppl[rA*36 + kpc + 4];
            ah[3] = Pph[(rA+8)*36 + kpc+4]; al[3] = Ppl[(rA+8)*36 + kpc+4];
            #pragma unroll
            for (int nt = 0; nt < 8; nt++){
                int d = nt*8 + (lane>>2);
                uint32_t b0h = Vhs[kpc*72 + d],     b1h = Vhs[(kpc+4)*72 + d];
                uint32_t b0l = Vls[kpc*72 + d],     b1l = Vls[(kpc+4)*72 + d];
                mma16(o[nt], ah, b0h, b1h);
                mma16(o[nt], ah, b0l, b1l);
                mma16(o[nt], al, b0h, b1h);
            }
        }
    }

    // epilogue: normalize and write g_O[b*M+m][h*64+d]
    const int b = bh >> 4, h = bh & 15;
    const float inv0 = 1.f / l_run[0], inv1 = 1.f / l_run[1];
    #pragma unroll
    for (int nt = 0; nt < 8; nt++){
        int d0 = nt*8 + ((lane&3)<<1);
        int m0 = q0 + rA;
        *(float2*)&g_O[((size_t)(b*MM + m0))*DD + h*64 + d0] =
            make_float2(o[nt][0]*inv0, o[nt][1]*inv0);
        *(float2*)&g_O[((size_t)(b*MM + m0 + 8))*DD + h*64 + d0] =
            make_float2(o[nt][2]*inv1, o[nt][3]*inv1);
    }
}

// ---------------------------------------------------------------------------
extern "C" void kernel_launch(void* const* d_in, const int* in_sizes, int n_in,
                              void* d_out, int out_size)
{
    const float* x   = (const float*)d_in[0];
    const float* P_i = (const float*)d_in[1];
    const float* P_o = (const float*)d_in[2];
    float* y = (float*)d_out;

    cudaFuncSetAttribute(attn_tc,
                         cudaFuncAttributeMaxDynamicSharedMemorySize,
                         ATTN_SMEM_BYTES);

    // 1) QKV projection: per batch X[1024,1024] @ P_i[1024,3072]
    {
        dim3 grid(N3/128, MM/128, BB);
        gemm_bf16x3<1><<<grid, 256>>>(x, P_i, nullptr, MM, N3, DD);
    }
    // 2) Causal flash attention (3x-bf16 tensor)
    {
        dim3 grid(MM/128, BB*HH);
        attn_tc<<<grid, 256, ATTN_SMEM_BYTES>>>();
    }
    // 3) Output projection: g_O[8192,1024] @ P_o[1024,1024] -> y
    {
        dim3 grid(DD/128, (BB*MM)/128, 1);
        gemm_bf16x3<2><<<grid, 256>>>(nullptr, P_o, y, BB*MM, DD, DD);
    }
}

// round 5
// speedup vs baseline: 2.4454x; 1.1566x over previous
#include <cuda_runtime.h>
#include <cuda_bf16.h>
#include <math.h>
#include <stdint.h>

#define BB 8
#define MM 1024
#define DD 1024
#define HH 16
#define KHD 64
#define N3 3072

// fp32 intermediates from QKV gemm
__device__ float g_Q[BB*HH*MM*KHD];
__device__ float g_K[BB*HH*MM*KHD];
__device__ float g_V[BB*HH*MM*KHD];

// pre-split packed bf16x2 hi/lo operands (u32 = two adjacent elements)
__device__ uint32_t g_xh [BB*MM*(DD/2)];     // [b*M+m][kp]   k-pairs
__device__ uint32_t g_xl [BB*MM*(DD/2)];
__device__ uint32_t g_Pih[(DD/2)*N3];        // [kp][n]       k-pairs, n contig
__device__ uint32_t g_Pil[(DD/2)*N3];
__device__ uint32_t g_Poh[(DD/2)*DD];
__device__ uint32_t g_Pol[(DD/2)*DD];
__device__ uint32_t g_Qh [BB*HH*MM*(KHD/2)]; // [bh][m][dp]   d-pairs
__device__ uint32_t g_Ql [BB*HH*MM*(KHD/2)];
__device__ uint32_t g_Kh [BB*HH*MM*(KHD/2)];
__device__ uint32_t g_Kl [BB*HH*MM*(KHD/2)];
__device__ uint32_t g_Vph[BB*HH*(MM/2)*KHD]; // [bh][mp][d]   key-pairs
__device__ uint32_t g_Vpl[BB*HH*(MM/2)*KHD];
__device__ uint32_t g_Oh [BB*MM*(DD/2)];     // [b*M+m][dp]
__device__ uint32_t g_Ol [BB*MM*(DD/2)];

// ---------------------------------------------------------------------------
__device__ __forceinline__ uint32_t bpack(float x, float y){
    __nv_bfloat162 h = __floats2bfloat162_rn(x, y);
    return *reinterpret_cast<uint32_t*>(&h);
}
__device__ __forceinline__ uint32_t bsplit(float x, float y, float& rx, float& ry){
    __nv_bfloat162 h = __floats2bfloat162_rn(x, y);
    rx = x - __low2float(h);
    ry = y - __high2float(h);
    return *reinterpret_cast<uint32_t*>(&h);
}
__device__ __forceinline__ void mma16(float* d, const uint32_t* a,
                                      uint32_t b0, uint32_t b1){
    asm volatile("mma.sync.aligned.m16n8k16.row.col.f32.bf16.bf16.f32 "
        "{%0,%1,%2,%3},{%4,%5,%6,%7},{%8,%9},{%0,%1,%2,%3};"
        : "+f"(d[0]), "+f"(d[1]), "+f"(d[2]), "+f"(d[3])
        : "r"(a[0]), "r"(a[1]), "r"(a[2]), "r"(a[3]), "r"(b0), "r"(b1));
}
__device__ __forceinline__ uint32_t smem_u32(const void* p){
    uint32_t a;
    asm("{ .reg .u64 t; cvta.to.shared.u64 t, %1; cvt.u32.u64 %0, t; }"
        : "=r"(a) : "l"(p));
    return a;
}
__device__ __forceinline__ void cpa16(uint32_t dst, const void* src){
    asm volatile("cp.async.ca.shared.global [%0], [%1], 16;"
                 :: "r"(dst), "l"(src) : "memory");
}
#define CP_COMMIT() asm volatile("cp.async.commit_group;" ::: "memory")
#define CP_WAIT1()  asm volatile("cp.async.wait_group 1;" ::: "memory")
#define CP_WAIT0()  asm volatile("cp.async.wait_group 0;" ::: "memory")

// ---------------------------------------------------------------------------
// Pre-pass splitters
// ---------------------------------------------------------------------------
__global__ void split_contig(const float* __restrict__ src,
                             uint32_t* __restrict__ dh,
                             uint32_t* __restrict__ dl, int n){
    int i = blockIdx.x*256 + threadIdx.x;
    if (i >= n) return;
    float2 v = ((const float2*)src)[i];
    float rx, ry;
    dh[i] = bsplit(v.x, v.y, rx, ry);
    dl[i] = bpack(rx, ry);
}
// dst[kp][c] = pack(src[2kp][c], src[2kp+1][c]); N = row width
__global__ void split_strided(const float* __restrict__ src,
                              uint32_t* __restrict__ dh,
                              uint32_t* __restrict__ dl, int N, int n){
    int i = blockIdx.x*256 + threadIdx.x;
    if (i >= n) return;
    int kp = i / N, c = i - kp*N;
    float a = src[(size_t)(2*kp)*N + c];
    float b = src[(size_t)(2*kp+1)*N + c];
    float rx, ry;
    dh[i] = bsplit(a, b, rx, ry);
    dl[i] = bpack(rx, ry);
}
// Q,K: d-pairs (contig).  V: key-pairs (stride KHD).
__global__ void split_qkv(int n){
    int i = blockIdx.x*256 + threadIdx.x;
    if (i >= n) return;
    float rx, ry;
    float2 q = ((const float2*)g_Q)[i];
    g_Qh[i] = bsplit(q.x, q.y, rx, ry);  g_Ql[i] = bpack(rx, ry);
    float2 k = ((const float2*)g_K)[i];
    g_Kh[i] = bsplit(k.x, k.y, rx, ry);  g_Kl[i] = bpack(rx, ry);
    int mp = i >> 6, d = i & 63;
    float v0 = g_V[(size_t)(2*mp)*KHD + d];
    float v1 = g_V[(size_t)(2*mp+1)*KHD + d];
    g_Vph[i] = bsplit(v0, v1, rx, ry);   g_Vpl[i] = bpack(rx, ry);
}

// ---------------------------------------------------------------------------
// 3x-bf16 GEMM, pre-split operands, cp.async double buffering.
// CTA tile 128x128, k-tile 32 (16 kp). 256 threads, 8 warps (2m x 4n),
// warp tile 64x32 -> 4mt x 4nt m16n8k16, 3 products (hh, hl, lh).
// smem per buffer (u32): sAh[128][20] sAl | sBh[16][136] sBl  = 9472 u32
// MODE 1: QKV (A = g_x* batch slice, scatter fp32 -> g_Q/g_K/g_V)
// MODE 2: proj (A = g_O*, C = y)
// ---------------------------------------------------------------------------
#define GBUF 9472
#define GEMM_SMEM_BYTES (2*GBUF*4)

template<int MODE>
__global__ __launch_bounds__(256, 2) void gemm_b3(
    const uint32_t* __restrict__ AH, const uint32_t* __restrict__ AL,
    const uint32_t* __restrict__ BH, const uint32_t* __restrict__ BL,
    float* __restrict__ C, int Mx, int Nx, int Kx)
{
    extern __shared__ uint32_t smg[];
    const uint32_t sb = smem_u32(smg);
    const int tid = threadIdx.x, lane = tid & 31, wid = tid >> 5;
    const int wm = wid >> 2, wn = wid & 3;
    const int bm = blockIdx.y, bn = blockIdx.x, bz = blockIdx.z;
    const int Kp = Kx >> 1;

    const uint32_t* Ah = AH + (size_t)bz * Mx * Kp;
    const uint32_t* Al = AL + (size_t)bz * Mx * Kp;

    const int nT = Kx >> 5;

    // per-thread copy coordinates
    const int ar0 = tid >> 2, ac4 = (tid & 3) << 2;          // +256 -> ar0+64
    const int bk0 = tid >> 5, bn4 = (tid & 31) << 2;         // +256 -> bk0+8

    auto issue = [&](int t){
        const int kp0 = t << 4;
        const uint32_t d0 = sb + (t & 1)*GBUF*4;
        // A: rows ar0, ar0+64; 16 u32 per row at pitch 20
        cpa16(d0 + (ar0*20 + ac4)*4,            Ah + (size_t)(bm*128 + ar0)*Kp + kp0 + ac4);
        cpa16(d0 + ((ar0+64)*20 + ac4)*4,       Ah + (size_t)(bm*128 + ar0+64)*Kp + kp0 + ac4);
        cpa16(d0 + (2560 + ar0*20 + ac4)*4,     Al + (size_t)(bm*128 + ar0)*Kp + kp0 + ac4);
        cpa16(d0 + (2560 + (ar0+64)*20 + ac4)*4,Al + (size_t)(bm*128 + ar0+64)*Kp + kp0 + ac4);
        // B: kp rows bk0, bk0+8; 128 u32 per row at pitch 136
        cpa16(d0 + (5120 + bk0*136 + bn4)*4,    BH + (size_t)(kp0 + bk0)*Nx + bn*128 + bn4);
        cpa16(d0 + (5120 + (bk0+8)*136 + bn4)*4,BH + (size_t)(kp0 + bk0+8)*Nx + bn*128 + bn4);
        cpa16(d0 + (7296 + bk0*136 + bn4)*4,    BL + (size_t)(kp0 + bk0)*Nx + bn*128 + bn4);
        cpa16(d0 + (7296 + (bk0+8)*136 + bn4)*4,BL + (size_t)(kp0 + bk0+8)*Nx + bn*128 + bn4);
        CP_COMMIT();
    };

    float acc[4][4][4];
    #pragma unroll
    for (int mt = 0; mt < 4; mt++)
        #pragma unroll
        for (int nt = 0; nt < 4; nt++)
            #pragma unroll
            for (int c = 0; c < 4; c++) acc[mt][nt][c] = 0.f;

    issue(0);
    for (int t = 0; t < nT; ++t){
        if (t + 1 < nT){ issue(t + 1); CP_WAIT1(); }
        else           { CP_WAIT0(); }
        __syncthreads();

        uint32_t* sAh = smg + (t & 1)*GBUF;
        uint32_t* sAl = sAh + 2560;
        uint32_t* sBh = sAh + 5120;
        uint32_t* sBl = sAh + 7296;

        #pragma unroll
        for (int kk = 0; kk < 2; kk++){
            uint32_t afh[4][4], afl[4][4];
            const int c0 = kk*8 + (lane & 3);
            #pragma unroll
            for (int mt = 0; mt < 4; mt++){
                const int r0 = wm*64 + mt*16 + (lane >> 2);
                afh[mt][0] = sAh[r0*20 + c0];       afl[mt][0] = sAl[r0*20 + c0];
                afh[mt][1] = sAh[(r0+8)*20 + c0];   afl[mt][1] = sAl[(r0+8)*20 + c0];
                afh[mt][2] = sAh[r0*20 + c0+4];     afl[mt][2] = sAl[r0*20 + c0+4];
                afh[mt][3] = sAh[(r0+8)*20 + c0+4]; afl[mt][3] = sAl[(r0+8)*20 + c0+4];
            }
            const int kr = kk*8 + (lane & 3);
            #pragma unroll
            for (int nt = 0; nt < 4; nt++){
                const int nc = wn*32 + nt*8 + (lane >> 2);
                uint32_t b0h = sBh[kr*136 + nc], b1h = sBh[(kr+4)*136 + nc];
                uint32_t b0l = sBl[kr*136 + nc], b1l = sBl[(kr+4)*136 + nc];
                #pragma unroll
                for (int mt = 0; mt < 4; mt++){
                    mma16(acc[mt][nt], afh[mt], b0h, b1h);
                    mma16(acc[mt][nt], afh[mt], b0l, b1l);
                    mma16(acc[mt][nt], afl[mt], b0h, b1h);
                }
            }
        }
        __syncthreads();
    }

    if (MODE == 1){
        #pragma unroll
        for (int mt = 0; mt < 4; mt++)
            #pragma unroll
            for (int nt = 0; nt < 4; nt++)
                #pragma unroll
                for (int c = 0; c < 4; c++){
                    int row = bm*128 + wm*64 + mt*16 + (lane>>2) + ((c>>1)<<3);
                    int col = bn*128 + wn*32 + nt*8 + ((lane&3)<<1) + (c&1);
                    int h = col / 192;
                    int r = col - h*192;
                    size_t base = ((size_t)((bz*HH + h)*MM + row))*KHD;
                    float v = acc[mt][nt][c];
                    if (r < 64)        g_Q[base + r]        = v;
                    else if (r < 128)  g_K[base + r - 64]   = v;
                    else               g_V[base + r - 128]  = v;
                }
    } else {
        #pragma unroll
        for (int mt = 0; mt < 4; mt++)
            #pragma unroll
            for (int nt = 0; nt < 4; nt++){
                int row = bm*128 + wm*64 + mt*16 + (lane>>2);
                int col = bn*128 + wn*32 + nt*8 + ((lane&3)<<1);
                *(float2*)&C[(size_t)row*Nx + col] =
                    make_float2(acc[mt][nt][0], acc[mt][nt][1]);
                *(float2*)&C[(size_t)(row+8)*Nx + col] =
                    make_float2(acc[mt][nt][2], acc[mt][nt][3]);
            }
    }
}

// ---------------------------------------------------------------------------
// 3x-bf16 causal flash attention, pre-split inputs. 256 threads, q-tile 128,
// kv-tile 64. Tile loads are pure u32 copies; Q frags direct LDG; epilogue
// writes O as packed hi/lo pairs for the proj gemm.
// smem (u32): Pph[128][36] Ppl | Khs[32][73] Kls | Vhs[32][72] Vls
// ---------------------------------------------------------------------------
#define ATTN_SMEM_U32 (2*128*36 + 2*32*73 + 2*32*72)
#define ATTN_SMEM_BYTES (ATTN_SMEM_U32*4)

__global__ __launch_bounds__(256, 2) void attn_tc()
{
    extern __shared__ uint32_t smu[];
    uint32_t* Pph = smu;                   // [128][36]
    uint32_t* Ppl = Pph + 128*36;
    uint32_t* Khs = Ppl + 128*36;          // [32][73]
    uint32_t* Kls = Khs + 32*73;
    uint32_t* Vhs = Kls + 32*73;           // [32][72]
    uint32_t* Vls = Vhs + 32*72;

    const int tid = threadIdx.x, lane = tid & 31, wid = tid >> 5;
    const int qt = gridDim.x - 1 - blockIdx.x;
    const int bh = blockIdx.y;
    const int q0 = qt * 128;

    const uint32_t* Qh_g = g_Qh + (size_t)bh*MM*32;
    const uint32_t* Ql_g = g_Ql + (size_t)bh*MM*32;
    const uint32_t* Kh_g = g_Kh + (size_t)bh*MM*32;
    const uint32_t* Kl_g = g_Kl + (size_t)bh*MM*32;
    const uint32_t* Vh_g = g_Vph + (size_t)bh*(MM/2)*KHD;
    const uint32_t* Vl_g = g_Vpl + (size_t)bh*(MM/2)*KHD;

    const int rA = wid*16 + (lane>>2);

    // Q frags: direct loads of packed pairs
    uint32_t qh[4][4], ql[4][4];
    #pragma unroll
    for (int kk = 0; kk < 4; kk++){
        int dp = kk*8 + (lane & 3);
        qh[kk][0] = Qh_g[(size_t)(q0+rA)*32 + dp];
        qh[kk][1] = Qh_g[(size_t)(q0+rA+8)*32 + dp];
        qh[kk][2] = Qh_g[(size_t)(q0+rA)*32 + dp+4];
        qh[kk][3] = Qh_g[(size_t)(q0+rA+8)*32 + dp+4];
        ql[kk][0] = Ql_g[(size_t)(q0+rA)*32 + dp];
        ql[kk][1] = Ql_g[(size_t)(q0+rA+8)*32 + dp];
        ql[kk][2] = Ql_g[(size_t)(q0+rA)*32 + dp+4];
        ql[kk][3] = Ql_g[(size_t)(q0+rA+8)*32 + dp+4];
    }

    float o[8][4];
    #pragma unroll
    for (int nt = 0; nt < 8; nt++)
        #pragma unroll
        for (int c = 0; c < 4; c++) o[nt][c] = 0.f;
    float m_run[2] = {-1e30f, -1e30f};
    float l_run[2] = {0.f, 0.f};

    const int ktEnd = 2*qt + 1;
    for (int kt = 0; kt <= ktEnd; kt++){
        const int k0 = kt*64;
        __syncthreads();
        // K transposed to [dp][key]; V straight [kp][d]
        #pragma unroll
        for (int it = 0; it < 8; it++){
            int idx = tid + it*256;
            int key = idx >> 5, dp = idx & 31;
            Khs[dp*73 + key] = Kh_g[(size_t)(k0+key)*32 + dp];
            Kls[dp*73 + key] = Kl_g[(size_t)(k0+key)*32 + dp];
            int kp = idx >> 6, d = idx & 63;
            Vhs[kp*72 + d] = Vh_g[(size_t)((k0>>1)+kp)*64 + d];
            Vls[kp*72 + d] = Vl_g[(size_t)((k0>>1)+kp)*64 + d];
        }
        __syncthreads();

        float s[8][4];
        #pragma unroll
        for (int nt = 0; nt < 8; nt++)
            #pragma unroll
            for (int c = 0; c < 4; c++) s[nt][c] = 0.f;

        #pragma unroll
        for (int kk = 0; kk < 4; kk++){
            int dpc = kk*8 + (lane&3);
            #pragma unroll
            for (int nt = 0; nt < 8; nt++){
                int keyb = nt*8 + (lane>>2);
                uint32_t b0h = Khs[dpc*73 + keyb],     b1h = Khs[(dpc+4)*73 + keyb];
                uint32_t b0l = Kls[dpc*73 + keyb],     b1l = Kls[(dpc+4)*73 + keyb];
                mma16(s[nt], qh[kk], b0h, b1h);
                mma16(s[nt], qh[kk], b0l, b1l);
                mma16(s[nt], ql[kk], b0h, b1h);
            }
        }

        const bool needMask = (kt >= 2*qt);
        #pragma unroll
        for (int nt = 0; nt < 8; nt++)
            #pragma unroll
            for (int c = 0; c < 4; c++){
                int rowL = wid*16 + (lane>>2) + ((c>>1)<<3);
                int colL = nt*8 + ((lane&3)<<1) + (c&1);
                float v = s[nt][c] * 0.125f;
                if (needMask && (k0 + colL > q0 + rowL)) v = -1e30f;
                s[nt][c] = v;
            }

        #pragma unroll
        for (int hf = 0; hf < 2; hf++){
            float rm = -1e30f;
            #pragma unroll
            for (int nt = 0; nt < 8; nt++)
                rm = fmaxf(rm, fmaxf(s[nt][2*hf], s[nt][2*hf+1]));
            rm = fmaxf(rm, __shfl_xor_sync(0xffffffffu, rm, 1));
            rm = fmaxf(rm, __shfl_xor_sync(0xffffffffu, rm, 2));
            float mn  = fmaxf(m_run[hf], rm);
            float scl = __expf(m_run[hf] - mn);
            float psum = 0.f;
            #pragma unroll
            for (int nt = 0; nt < 8; nt++){
                float p0 = __expf(s[nt][2*hf]   - mn);
                float p1 = __expf(s[nt][2*hf+1] - mn);
                s[nt][2*hf] = p0; s[nt][2*hf+1] = p1;
                psum += p0 + p1;
            }
            psum += __shfl_xor_sync(0xffffffffu, psum, 1);
            psum += __shfl_xor_sync(0xffffffffu, psum, 2);
            l_run[hf] = l_run[hf]*scl + psum;
            m_run[hf] = mn;
            #pragma unroll
            for (int nt = 0; nt < 8; nt++){
                o[nt][2*hf]   *= scl;
                o[nt][2*hf+1] *= scl;
            }
        }

        #pragma unroll
        for (int nt = 0; nt < 8; nt++){
            int kp = nt*4 + (lane&3);
            float rx, ry;
            Pph[rA*36 + kp]     = bsplit(s[nt][0], s[nt][1], rx, ry);
            Ppl[rA*36 + kp]     = bpack(rx, ry);
            Pph[(rA+8)*36 + kp] = bsplit(s[nt][2], s[nt][3], rx, ry);
            Ppl[(rA+8)*36 + kp] = bpack(rx, ry);
        }
        __syncwarp();

        #pragma unroll
        for (int kk = 0; kk < 4; kk++){
            int kpc = kk*8 + (lane&3);
            uint32_t ah[4], al[4];
            ah[0] = Pph[rA*36 + kpc];       al[0] = Ppl[rA*36 + kpc];
            ah[1] = Pph[(rA+8)*36 + kpc];   al[1] = Ppl[(rA+8)*36 + kpc];
            ah[2] = Pph[rA*36 + kpc + 4];   al[2] = Ppl[rA*36 + kpc + 4];
            ah[3] = Pph[(rA+8)*36 + kpc+4]; al[3] = Ppl[(rA+8)*36 + kpc+4];
            #pragma unroll
            for (int nt = 0; nt < 8; nt++){
                int d = nt*8 + (lane>>2);
                uint32_t b0h = Vhs[kpc*72 + d],     b1h = Vhs[(kpc+4)*72 + d];
                uint32_t b0l = Vls[kpc*72 + d],     b1l = Vls[(kpc+4)*72 + d];
                mma16(o[nt], ah, b0h, b1h);
                mma16(o[nt], ah, b0l, b1l);
                mma16(o[nt], al, b0h, b1h);
            }
        }
    }

    // epilogue: normalize, split, write packed pairs for the proj gemm
    const int b = bh >> 4, h = bh & 15;
    const float inv0 = 1.f / l_run[0], inv1 = 1.f / l_run[1];
    const int m0 = q0 + rA;
    #pragma unroll
    for (int nt = 0; nt < 8; nt++){
        int dp = h*32 + nt*4 + (lane&3);
        float rx, ry;
        uint32_t hb = bsplit(o[nt][0]*inv0, o[nt][1]*inv0, rx, ry);
        g_Oh[(size_t)(b*MM + m0)*512 + dp] = hb;
        g_Ol[(size_t)(b*MM + m0)*512 + dp] = bpack(rx, ry);
        hb = bsplit(o[nt][2]*inv1, o[nt][3]*inv1, rx, ry);
        g_Oh[(size_t)(b*MM + m0 + 8)*512 + dp] = hb;
        g_Ol[(size_t)(b*MM + m0 + 8)*512 + dp] = bpack(rx, ry);
    }
}

// ---------------------------------------------------------------------------
extern "C" void kernel_launch(void* const* d_in, const int* in_sizes, int n_in,
                              void* d_out, int out_size)
{
    const float* x   = (const float*)d_in[0];
    const float* P_i = (const float*)d_in[1];
    const float* P_o = (const float*)d_in[2];
    float* y = (float*)d_out;

    uint32_t *xh, *xl, *pih, *pil, *poh, *pol, *oh, *ol;
    cudaGetSymbolAddress((void**)&xh,  g_xh);
    cudaGetSymbolAddress((void**)&xl,  g_xl);
    cudaGetSymbolAddress((void**)&pih, g_Pih);
    cudaGetSymbolAddress((void**)&pil, g_Pil);
    cudaGetSymbolAddress((void**)&poh, g_Poh);
    cudaGetSymbolAddress((void**)&pol, g_Pol);
    cudaGetSymbolAddress((void**)&oh,  g_Oh);
    cudaGetSymbolAddress((void**)&ol,  g_Ol);

    cudaFuncSetAttribute(gemm_b3<1>, cudaFuncAttributeMaxDynamicSharedMemorySize,
                         GEMM_SMEM_BYTES);
    cudaFuncSetAttribute(gemm_b3<2>, cudaFuncAttributeMaxDynamicSharedMemorySize,
                         GEMM_SMEM_BYTES);
    cudaFuncSetAttribute(attn_tc, cudaFuncAttributeMaxDynamicSharedMemorySize,
                         ATTN_SMEM_BYTES);

    // 0) pre-split inputs
    split_contig <<<(BB*MM*(DD/2))/256, 256>>>(x, xh, xl, BB*MM*(DD/2));
    split_strided<<<((DD/2)*N3)/256, 256>>>(P_i, pih, pil, N3, (DD/2)*N3);
    split_strided<<<((DD/2)*DD)/256, 256>>>(P_o, poh, pol, DD, (DD/2)*DD);

    // 1) QKV projection
    {
        dim3 grid(N3/128, MM/128, BB);
        gemm_b3<1><<<grid, 256, GEMM_SMEM_BYTES>>>(xh, xl, pih, pil,
                                                   nullptr, MM, N3, DD);
    }
    // 1.5) split Q/K/V into packed hi/lo operand layouts
    split_qkv<<<(BB*HH*MM*(KHD/2))/256, 256>>>(BB*HH*MM*(KHD/2));

    // 2) causal flash attention
    {
        dim3 grid(MM/128, BB*HH);
        attn_tc<<<grid, 256, ATTN_SMEM_BYTES>>>();
    }
    // 3) output projection
    {
        dim3 grid(DD/128, (BB*MM)/128, 1);
        gemm_b3<2><<<grid, 256, GEMM_SMEM_BYTES>>>(oh, ol, poh, pol,
                                                   y, BB*MM, DD, DD);
    }
}

// round 6
// speedup vs baseline: 2.5589x; 1.0464x over previous
#include <cuda_runtime.h>
#include <cuda_bf16.h>
#include <math.h>
#include <stdint.h>

#define BB 8
#define MM 1024
#define DD 1024
#define HH 16
#define KHD 64
#define N3 3072
#define KP 512   // k-pairs for K=1024

// fp32 V intermediate (only V needs a transpose pass)
__device__ float g_V[BB*HH*MM*KHD];

// pre-split packed bf16x2 hi/lo operands (u32 = two adjacent elements)
__device__ uint32_t g_xh [BB*MM*KP];        // [b*M+m][kp]
__device__ uint32_t g_xl [BB*MM*KP];
__device__ uint32_t g_Pih[N3*KP];           // [n][kp]  (transposed!)
__device__ uint32_t g_Pil[N3*KP];
__device__ uint32_t g_Poh[DD*KP];           // [n][kp]
__device__ uint32_t g_Pol[DD*KP];
__device__ uint32_t g_Qh [BB*HH*MM*32];     // [bh][m][dp]
__device__ uint32_t g_Ql [BB*HH*MM*32];
__device__ uint32_t g_Kh [BB*HH*MM*32];     // [bh][key][dp]
__device__ uint32_t g_Kl [BB*HH*MM*32];
__device__ uint32_t g_Vph[BB*HH*KHD*(MM/2)];// [bh][d][mp]  (transposed!)
__device__ uint32_t g_Vpl[BB*HH*KHD*(MM/2)];
__device__ uint32_t g_Oh [BB*MM*KP];        // [b*M+m][dp]
__device__ uint32_t g_Ol [BB*MM*KP];

// ---------------------------------------------------------------------------
__device__ __forceinline__ uint32_t bpack(float x, float y){
    __nv_bfloat162 h = __floats2bfloat162_rn(x, y);
    return *reinterpret_cast<uint32_t*>(&h);
}
__device__ __forceinline__ uint32_t bsplit(float x, float y, float& rx, float& ry){
    __nv_bfloat162 h = __floats2bfloat162_rn(x, y);
    rx = x - __low2float(h);
    ry = y - __high2float(h);
    return *reinterpret_cast<uint32_t*>(&h);
}
__device__ __forceinline__ void mma16(float* d, const uint32_t* a,
                                      uint32_t b0, uint32_t b1){
    asm volatile("mma.sync.aligned.m16n8k16.row.col.f32.bf16.bf16.f32 "
        "{%0,%1,%2,%3},{%4,%5,%6,%7},{%8,%9},{%0,%1,%2,%3};"
        : "+f"(d[0]), "+f"(d[1]), "+f"(d[2]), "+f"(d[3])
        : "r"(a[0]), "r"(a[1]), "r"(a[2]), "r"(a[3]), "r"(b0), "r"(b1));
}
__device__ __forceinline__ uint32_t smem_u32(const void* p){
    uint32_t a;
    asm("{ .reg .u64 t; cvta.to.shared.u64 t, %1; cvt.u32.u64 %0, t; }"
        : "=r"(a) : "l"(p));
    return a;
}
__device__ __forceinline__ void cpa16(uint32_t dst, const void* src){
    asm volatile("cp.async.ca.shared.global [%0], [%1], 16;"
                 :: "r"(dst), "l"(src) : "memory");
}
#define CP_COMMIT() asm volatile("cp.async.commit_group;" ::: "memory")
#define CP_WAIT1()  asm volatile("cp.async.wait_group 1;" ::: "memory")
#define CP_WAIT0()  asm volatile("cp.async.wait_group 0;" ::: "memory")
#define LDSM4(r0,r1,r2,r3,addr) asm volatile( \
    "ldmatrix.sync.aligned.m8n8.x4.shared.b16 {%0,%1,%2,%3}, [%4];" \
    : "=r"(r0), "=r"(r1), "=r"(r2), "=r"(r3) : "r"(addr))

// ---------------------------------------------------------------------------
// Pre-pass splitters
// ---------------------------------------------------------------------------
__global__ void split_contig(const float* __restrict__ src,
                             uint32_t* __restrict__ dh,
                             uint32_t* __restrict__ dl, int n){
    int i = blockIdx.x*256 + threadIdx.x;
    if (i >= n) return;
    float2 v = ((const float2*)src)[i];
    float rx, ry;
    dh[i] = bsplit(v.x, v.y, rx, ry);
    dl[i] = bpack(rx, ry);
}
// weights: src [K=1024][N] -> dst [n][kp] transposed, tiled via smem
__global__ void split_wT(const float* __restrict__ src,
                         uint32_t* __restrict__ dh,
                         uint32_t* __restrict__ dl, int N){
    __shared__ uint32_t sh[32][33], sl[32][33];
    const int kp0 = blockIdx.y*32, n0 = blockIdx.x*32;
    const int tx = threadIdx.x, ty = threadIdx.y;   // 32 x 8
    #pragma unroll
    for (int j = 0; j < 4; j++){
        int kpi = ty*4 + j;
        float a = src[(size_t)(2*(kp0+kpi))*N + n0 + tx];
        float b = src[(size_t)(2*(kp0+kpi)+1)*N + n0 + tx];
        float rx, ry;
        sh[kpi][tx] = bsplit(a, b, rx, ry);
        sl[kpi][tx] = bpack(rx, ry);
    }
    __syncthreads();
    #pragma unroll
    for (int j = 0; j < 4; j++){
        int ni = ty*4 + j;
        dh[(size_t)(n0+ni)*KP + kp0 + tx] = sh[tx][ni];
        dl[(size_t)(n0+ni)*KP + kp0 + tx] = sl[tx][ni];
    }
}
// V: g_V [bh][m][64] fp32 -> g_Vp [bh][d][mp] packed key-pairs (transposed)
__global__ void split_vT(){
    __shared__ uint32_t sh[32][65], sl[32][65];
    const int bh = blockIdx.y, mp0 = blockIdx.x*32;
    const float* V = g_V + (size_t)bh*MM*KHD;
    const int tid = threadIdx.x;
    #pragma unroll
    for (int it = 0; it < 8; it++){
        int idx = tid + it*256;
        int mp = idx >> 6, d = idx & 63;
        float a = V[(size_t)(2*(mp0+mp))*KHD + d];
        float b = V[(size_t)(2*(mp0+mp)+1)*KHD + d];
        float rx, ry;
        sh[mp][d] = bsplit(a, b, rx, ry);
        sl[mp][d] = bpack(rx, ry);
    }
    __syncthreads();
    uint32_t* oh = g_Vph + (size_t)bh*KHD*(MM/2);
    uint32_t* ol = g_Vpl + (size_t)bh*KHD*(MM/2);
    #pragma unroll
    for (int it = 0; it < 8; it++){
        int idx = tid + it*256;
        int d = idx >> 5, mpi = idx & 31;
        oh[(size_t)d*(MM/2) + mp0 + mpi] = sh[mpi][d];
        ol[(size_t)d*(MM/2) + mp0 + mpi] = sl[mpi][d];
    }
}

// ---------------------------------------------------------------------------
// 3x-bf16 GEMM with ldmatrix operand loads. CTA tile 128x128, k-tile 32.
// 256 threads, 8 warps (2m x 4n), warp tile 64x32. Both A and B in smem as
// [row][kp] pitch 20 u32 (LDSM phase-conflict-free). cp.async double-buffered.
// MODE 1: QKV — epilogue packs Q/K directly (d-pairs), V to fp32 g_V.
// MODE 2: proj — A = g_O packed, C = y fp32.
// ---------------------------------------------------------------------------
#define G_STAGE 10240   // u32: Ah 2560 | Al 2560 | Bh 2560 | Bl 2560
#define GEMM_SMEM_BYTES (2*G_STAGE*4)

template<int MODE>
__global__ __launch_bounds__(256, 2) void gemm_b3(
    const uint32_t* __restrict__ AH, const uint32_t* __restrict__ AL,
    const uint32_t* __restrict__ BH, const uint32_t* __restrict__ BL,
    float* __restrict__ C, int Mx, int Nx)
{
    extern __shared__ uint32_t smg[];
    const uint32_t sb = smem_u32(smg);
    const int tid = threadIdx.x, lane = tid & 31, wid = tid >> 5;
    const int wm = wid >> 2, wn = wid & 3;
    const int bm = blockIdx.y, bn = blockIdx.x, bz = blockIdx.z;

    const uint32_t* Ah = AH + (size_t)bz * Mx * KP;
    const uint32_t* Al = AL + (size_t)bz * Mx * KP;

    const int r = tid >> 2, ch4 = (tid & 3) << 2;   // copy coords

    auto issue = [&](int t){
        const int kp0 = t << 4;
        const uint32_t d0 = sb + ((t & 1)*G_STAGE)*4;
        cpa16(d0 + (r*20 + ch4)*4,              Ah + (size_t)(bm*128 + r)*KP + kp0 + ch4);
        cpa16(d0 + ((r+64)*20 + ch4)*4,         Ah + (size_t)(bm*128 + r+64)*KP + kp0 + ch4);
        cpa16(d0 + (2560 + r*20 + ch4)*4,       Al + (size_t)(bm*128 + r)*KP + kp0 + ch4);
        cpa16(d0 + (2560 + (r+64)*20 + ch4)*4,  Al + (size_t)(bm*128 + r+64)*KP + kp0 + ch4);
        cpa16(d0 + (5120 + r*20 + ch4)*4,       BH + (size_t)(bn*128 + r)*KP + kp0 + ch4);
        cpa16(d0 + (5120 + (r+64)*20 + ch4)*4,  BH + (size_t)(bn*128 + r+64)*KP + kp0 + ch4);
        cpa16(d0 + (7680 + r*20 + ch4)*4,       BL + (size_t)(bn*128 + r)*KP + kp0 + ch4);
        cpa16(d0 + (7680 + (r+64)*20 + ch4)*4,  BL + (size_t)(bn*128 + r+64)*KP + kp0 + ch4);
        CP_COMMIT();
    };

    float acc[4][4][4];
    #pragma unroll
    for (int mt = 0; mt < 4; mt++)
        #pragma unroll
        for (int nt = 0; nt < 4; nt++)
            #pragma unroll
            for (int c = 0; c < 4; c++) acc[mt][nt][c] = 0.f;

    const uint32_t lrow = (lane & 15), lcol = ((lane >> 4) << 2);
    const int nT = 32;   // K=1024 / 32

    issue(0);
    for (int t = 0; t < nT; ++t){
        if (t + 1 < nT){ issue(t + 1); CP_WAIT1(); }
        else           { CP_WAIT0(); }
        __syncthreads();

        const uint32_t st = sb + ((t & 1)*G_STAGE)*4;
        #pragma unroll
        for (int kk = 0; kk < 2; kk++){
            const uint32_t fo = (lrow*20 + kk*8 + lcol)*4;
            uint32_t ah_[4][4], al_[4][4];
            #pragma unroll
            for (int mt = 0; mt < 4; mt++){
                const uint32_t ra = st + ((wm*64 + mt*16)*20)*4 + fo;
                LDSM4(ah_[mt][0], ah_[mt][1], ah_[mt][2], ah_[mt][3], ra);
                LDSM4(al_[mt][0], al_[mt][1], al_[mt][2], al_[mt][3], ra + 2560*4);
            }
            #pragma unroll
            for (int ntp = 0; ntp < 2; ntp++){
                const uint32_t rb = st + (5120 + (wn*32 + ntp*16)*20)*4 + fo;
                uint32_t bh0, bh1, bh2, bh3, bl0, bl1, bl2, bl3;
                LDSM4(bh0, bh1, bh2, bh3, rb);
                LDSM4(bl0, bl1, bl2, bl3, rb + 2560*4);
                #pragma unroll
                for (int mt = 0; mt < 4; mt++){
                    mma16(acc[mt][2*ntp],   ah_[mt], bh0, bh2);
                    mma16(acc[mt][2*ntp],   ah_[mt], bl0, bl2);
                    mma16(acc[mt][2*ntp],   al_[mt], bh0, bh2);
                    mma16(acc[mt][2*ntp+1], ah_[mt], bh1, bh3);
                    mma16(acc[mt][2*ntp+1], ah_[mt], bl1, bl3);
                    mma16(acc[mt][2*ntp+1], al_[mt], bh1, bh3);
                }
            }
        }
        __syncthreads();
    }

    if (MODE == 1){
        #pragma unroll
        for (int mt = 0; mt < 4; mt++)
            #pragma unroll
            for (int nt = 0; nt < 4; nt++){
                const int col0 = bn*128 + wn*32 + nt*8 + ((lane&3)<<1);
                const int h = col0 / 192;
                const int rr = col0 - 192*h;
                #pragma unroll
                for (int half = 0; half < 2; half++){
                    const int row = bm*128 + wm*64 + mt*16 + (lane>>2) + half*8;
                    const size_t mi = (size_t)((bz*HH + h)*MM + row);
                    const float v0 = acc[mt][nt][2*half], v1 = acc[mt][nt][2*half+1];
                    if (rr < 64){
                        float rx, ry;
                        g_Qh[mi*32 + (rr>>1)] = bsplit(v0, v1, rx, ry);
                        g_Ql[mi*32 + (rr>>1)] = bpack(rx, ry);
                    } else if (rr < 128){
                        float rx, ry;
                        g_Kh[mi*32 + ((rr-64)>>1)] = bsplit(v0, v1, rx, ry);
                        g_Kl[mi*32 + ((rr-64)>>1)] = bpack(rx, ry);
                    } else {
                        g_V[mi*KHD + (rr-128)]     = v0;
                        g_V[mi*KHD + (rr-128) + 1] = v1;
                    }
                }
            }
    } else {
        #pragma unroll
        for (int mt = 0; mt < 4; mt++)
            #pragma unroll
            for (int nt = 0; nt < 4; nt++){
                int row = bm*128 + wm*64 + mt*16 + (lane>>2);
                int col = bn*128 + wn*32 + nt*8 + ((lane&3)<<1);
                *(float2*)&C[(size_t)row*Nx + col] =
                    make_float2(acc[mt][nt][0], acc[mt][nt][1]);
                *(float2*)&C[(size_t)(row+8)*Nx + col] =
                    make_float2(acc[mt][nt][2], acc[mt][nt][3]);
            }
    }
}

// ---------------------------------------------------------------------------
// 3x-bf16 causal flash attention: ldmatrix operands, no P smem, cp.async
// double-buffered K/V tiles. 256 threads, q-tile 128, kv-tile 64.
// smem stage (u32): Kh[64][36] | Kl | Vh[64][36] | Vl  = 9216; x2 stages.
// ---------------------------------------------------------------------------
#define A_STAGE 9216
#define ATTN_SMEM_BYTES (2*A_STAGE*4)

__global__ __launch_bounds__(256, 2) void attn_tc()
{
    extern __shared__ uint32_t smu[];
    const uint32_t sb = smem_u32(smu);

    const int tid = threadIdx.x, lane = tid & 31, wid = tid >> 5;
    const int qt = gridDim.x - 1 - blockIdx.x;
    const int bh = blockIdx.y;
    const int q0 = qt * 128;

    const uint32_t* Qh_g = g_Qh + (size_t)bh*MM*32;
    const uint32_t* Ql_g = g_Ql + (size_t)bh*MM*32;
    const uint32_t* Kh_g = g_Kh + (size_t)bh*MM*32;
    const uint32_t* Kl_g = g_Kl + (size_t)bh*MM*32;
    const uint32_t* Vh_g = g_Vph + (size_t)bh*KHD*(MM/2);
    const uint32_t* Vl_g = g_Vpl + (size_t)bh*KHD*(MM/2);

    const int rA = wid*16 + (lane>>2);

    uint32_t qh[4][4], ql[4][4];
    #pragma unroll
    for (int kk = 0; kk < 4; kk++){
        int dp = kk*8 + (lane & 3);
        qh[kk][0] = Qh_g[(size_t)(q0+rA)*32 + dp];
        qh[kk][1] = Qh_g[(size_t)(q0+rA+8)*32 + dp];
        qh[kk][2] = Qh_g[(size_t)(q0+rA)*32 + dp+4];
        qh[kk][3] = Qh_g[(size_t)(q0+rA+8)*32 + dp+4];
        ql[kk][0] = Ql_g[(size_t)(q0+rA)*32 + dp];
        ql[kk][1] = Ql_g[(size_t)(q0+rA+8)*32 + dp];
        ql[kk][2] = Ql_g[(size_t)(q0+rA)*32 + dp+4];
        ql[kk][3] = Ql_g[(size_t)(q0+rA+8)*32 + dp+4];
    }

    const int crow = tid >> 3, cch = (tid & 7) << 2;   // copy coords (2 rows each)
    auto issue = [&](int kt){
        const int k0 = kt*64;
        const uint32_t d0 = sb + ((kt & 1)*A_STAGE)*4;
        #pragma unroll
        for (int p = 0; p < 2; p++){
            const int rw = crow + p*32;
            cpa16(d0 + (rw*36 + cch)*4,          Kh_g + (size_t)(k0+rw)*32 + cch);
            cpa16(d0 + (2304 + rw*36 + cch)*4,   Kl_g + (size_t)(k0+rw)*32 + cch);
            cpa16(d0 + (4608 + rw*36 + cch)*4,   Vh_g + (size_t)rw*(MM/2) + (k0>>1) + cch);
            cpa16(d0 + (6912 + rw*36 + cch)*4,   Vl_g + (size_t)rw*(MM/2) + (k0>>1) + cch);
        }
        CP_COMMIT();
    };

    float o[8][4];
    #pragma unroll
    for (int nt = 0; nt < 8; nt++)
        #pragma unroll
        for (int c = 0; c < 4; c++) o[nt][c] = 0.f;
    float m_run[2] = {-1e30f, -1e30f};
    float l_run[2] = {0.f, 0.f};

    const uint32_t lrow = (lane & 15), lcol = ((lane >> 4) << 2);
    const int ktEnd = 2*qt + 1;

    issue(0);
    issue(1);
    for (int kt = 0; kt <= ktEnd; kt++){
        const int k0 = kt*64;
        if (kt < ktEnd) CP_WAIT1(); else CP_WAIT0();
        __syncthreads();

        const uint32_t st = sb + ((kt & 1)*A_STAGE)*4;

        // S = Q @ K^T
        float s[8][4];
        #pragma unroll
        for (int nt = 0; nt < 8; nt++)
            #pragma unroll
            for (int c = 0; c < 4; c++) s[nt][c] = 0.f;

        #pragma unroll
        for (int kk = 0; kk < 4; kk++){
            const uint32_t fo = (lrow*36 + kk*8 + lcol)*4;
            #pragma unroll
            for (int ntp = 0; ntp < 4; ntp++){
                const uint32_t ra = st + ((ntp*16)*36)*4 + fo;
                uint32_t h0, h1, h2, h3, l0, l1, l2, l3;
                LDSM4(h0, h1, h2, h3, ra);
                LDSM4(l0, l1, l2, l3, ra + 2304*4);
                mma16(s[2*ntp],   qh[kk], h0, h2);
                mma16(s[2*ntp],   qh[kk], l0, l2);
                mma16(s[2*ntp],   ql[kk], h0, h2);
                mma16(s[2*ntp+1], qh[kk], h1, h3);
                mma16(s[2*ntp+1], qh[kk], l1, l3);
                mma16(s[2*ntp+1], ql[kk], h1, h3);
            }
        }

        // scale + causal mask
        const bool needMask = (kt >= 2*qt);
        #pragma unroll
        for (int nt = 0; nt < 8; nt++)
            #pragma unroll
            for (int c = 0; c < 4; c++){
                int rowL = wid*16 + (lane>>2) + ((c>>1)<<3);
                int colL = nt*8 + ((lane&3)<<1) + (c&1);
                float v = s[nt][c] * 0.125f;
                if (needMask && (k0 + colL > q0 + rowL)) v = -1e30f;
                s[nt][c] = v;
            }

        // online softmax per row-half
        #pragma unroll
        for (int hf = 0; hf < 2; hf++){
            float rm = -1e30f;
            #pragma unroll
            for (int nt = 0; nt < 8; nt++)
                rm = fmaxf(rm, fmaxf(s[nt][2*hf], s[nt][2*hf+1]));
            rm = fmaxf(rm, __shfl_xor_sync(0xffffffffu, rm, 1));
            rm = fmaxf(rm, __shfl_xor_sync(0xffffffffu, rm, 2));
            float mn  = fmaxf(m_run[hf], rm);
            float scl = __expf(m_run[hf] - mn);
            float psum = 0.f;
            #pragma unroll
            for (int nt = 0; nt < 8; nt++){
                float p0 = __expf(s[nt][2*hf]   - mn);
                float p1 = __expf(s[nt][2*hf+1] - mn);
                s[nt][2*hf] = p0; s[nt][2*hf+1] = p1;
                psum += p0 + p1;
            }
            psum += __shfl_xor_sync(0xffffffffu, psum, 1);
            psum += __shfl_xor_sync(0xffffffffu, psum, 2);
            l_run[hf] = l_run[hf]*scl + psum;
            m_run[hf] = mn;
            #pragma unroll
            for (int nt = 0; nt < 8; nt++){
                o[nt][2*hf]   *= scl;
                o[nt][2*hf+1] *= scl;
            }
        }

        // O += P @ V  (P frags straight from registers)
        #pragma unroll
        for (int kk = 0; kk < 4; kk++){
            uint32_t ah[4], al[4];
            float rx, ry;
            ah[0] = bsplit(s[2*kk][0],   s[2*kk][1],   rx, ry); al[0] = bpack(rx, ry);
            ah[1] = bsplit(s[2*kk][2],   s[2*kk][3],   rx, ry); al[1] = bpack(rx, ry);
            ah[2] = bsplit(s[2*kk+1][0], s[2*kk+1][1], rx, ry); al[2] = bpack(rx, ry);
            ah[3] = bsplit(s[2*kk+1][2], s[2*kk+1][3], rx, ry); al[3] = bpack(rx, ry);
            const uint32_t fo = (lrow*36 + kk*8 + lcol)*4;
            #pragma unroll
            for (int ntp = 0; ntp < 4; ntp++){
                const uint32_t rv = st + (4608 + (ntp*16)*36)*4 + fo;
                uint32_t h0, h1, h2, h3, l0, l1, l2, l3;
                LDSM4(h0, h1, h2, h3, rv);
                LDSM4(l0, l1, l2, l3, rv + 2304*4);
                mma16(o[2*ntp],   ah, h0, h2);
                mma16(o[2*ntp],   ah, l0, l2);
                mma16(o[2*ntp],   al, h0, h2);
                mma16(o[2*ntp+1], ah, h1, h3);
                mma16(o[2*ntp+1], ah, l1, l3);
                mma16(o[2*ntp+1], al, h1, h3);
            }
        }
        __syncthreads();
        if (kt + 2 <= ktEnd) issue(kt + 2);
    }

    // epilogue: normalize, split, write packed pairs for the proj gemm
    const int b = bh >> 4, h = bh & 15;
    const float inv0 = 1.f / l_run[0], inv1 = 1.f / l_run[1];
    const int m0 = q0 + rA;
    #pragma unroll
    for (int nt = 0; nt < 8; nt++){
        int dp = h*32 + nt*4 + (lane&3);
        float rx, ry;
        uint32_t hb = bsplit(o[nt][0]*inv0, o[nt][1]*inv0, rx, ry);
        g_Oh[(size_t)(b*MM + m0)*KP + dp] = hb;
        g_Ol[(size_t)(b*MM + m0)*KP + dp] = bpack(rx, ry);
        hb = bsplit(o[nt][2]*inv1, o[nt][3]*inv1, rx, ry);
        g_Oh[(size_t)(b*MM + m0 + 8)*KP + dp] = hb;
        g_Ol[(size_t)(b*MM + m0 + 8)*KP + dp] = bpack(rx, ry);
    }
}

// ---------------------------------------------------------------------------
extern "C" void kernel_launch(void* const* d_in, const int* in_sizes, int n_in,
                              void* d_out, int out_size)
{
    const float* x   = (const float*)d_in[0];
    const float* P_i = (const float*)d_in[1];
    const float* P_o = (const float*)d_in[2];
    float* y = (float*)d_out;

    uint32_t *xh, *xl, *pih, *pil, *poh, *pol, *oh, *ol;
    cudaGetSymbolAddress((void**)&xh,  g_xh);
    cudaGetSymbolAddress((void**)&xl,  g_xl);
    cudaGetSymbolAddress((void**)&pih, g_Pih);
    cudaGetSymbolAddress((void**)&pil, g_Pil);
    cudaGetSymbolAddress((void**)&poh, g_Poh);
    cudaGetSymbolAddress((void**)&pol, g_Pol);
    cudaGetSymbolAddress((void**)&oh,  g_Oh);
    cudaGetSymbolAddress((void**)&ol,  g_Ol);

    cudaFuncSetAttribute(gemm_b3<1>, cudaFuncAttributeMaxDynamicSharedMemorySize,
                         GEMM_SMEM_BYTES);
    cudaFuncSetAttribute(gemm_b3<2>, cudaFuncAttributeMaxDynamicSharedMemorySize,
                         GEMM_SMEM_BYTES);
    cudaFuncSetAttribute(attn_tc, cudaFuncAttributeMaxDynamicSharedMemorySize,
                         ATTN_SMEM_BYTES);

    // 0) pre-split inputs (weights transposed to [n][kp])
    split_contig<<<(BB*MM*KP)/256, 256>>>(x, xh, xl, BB*MM*KP);
    {
        dim3 g(N3/32, KP/32); dim3 b(32, 8);
        split_wT<<<g, b>>>(P_i, pih, pil, N3);
    }
    {
        dim3 g(DD/32, KP/32); dim3 b(32, 8);
        split_wT<<<g, b>>>(P_o, poh, pol, DD);
    }
    // 1) QKV projection (Q/K packed directly; V fp32)
    {
        dim3 grid(N3/128, MM/128, BB);
        gemm_b3<1><<<grid, 256, GEMM_SMEM_BYTES>>>(xh, xl, pih, pil,
                                                   nullptr, MM, N3);
    }
    // 1.5) V transpose-split -> [d][mp]
    {
        dim3 g(MM/64, BB*HH);
        split_vT<<<g, 256>>>();
    }
    // 2) causal flash attention
    {
        dim3 grid(MM/128, BB*HH);
        attn_tc<<<grid, 256, ATTN_SMEM_BYTES>>>();
    }
    // 3) output projection
    {
        dim3 grid(DD/128, (BB*MM)/128, 1);
        gemm_b3<2><<<grid, 256, GEMM_SMEM_BYTES>>>(oh, ol, poh, pol,
                                                   y, BB*MM, DD);
    }
}